// round 1
// baseline (speedup 1.0000x reference)
#include <cuda_runtime.h>
#include <math.h>

#define NN 50000
#define EE 800000
#define CC 100000
#define DD 128

// ---------------- scratch (static __device__, no allocation) ----------------
static __device__ float g_agg[NN * DD];
static __device__ float g_h0[NN * DD];
static __device__ float g_h1[NN * DD];
static __device__ int   g_rowptr[NN + 1];
static __device__ int   g_cursor[NN];
static __device__ int   g_cnt[NN];
static __device__ int   g_col[EE];
static __device__ float g_invdeg[NN];
static __device__ unsigned g_umax;
static __device__ float g_sum;

// ---------------- helpers ----------------
__device__ __forceinline__ float lrelu(float v) { return v > 0.f ? v : 0.01f * v; }

__device__ __forceinline__ float postact(float v, int fix) {
    v = v > 0.f ? v : 0.01f * v;
    if (fix) {
        if (isnan(v)) v = 1e-14f;
        else if (isinf(v)) v = v > 0.f ? 3.4028234663852886e38f : -3.4028234663852886e38f;
    }
    return v;
}

__device__ __forceinline__ unsigned fkey(float f) {
    unsigned u = __float_as_uint(f);
    return (u & 0x80000000u) ? ~u : (u | 0x80000000u);
}
__device__ __forceinline__ float fdec(unsigned u) {
    return (u & 0x80000000u) ? __uint_as_float(u & 0x7fffffffu) : __uint_as_float(~u);
}

// ---------------- CSR build ----------------
__global__ void k_zero_cnt() {
    int i = blockIdx.x * blockDim.x + threadIdx.x;
    if (i < NN) g_cnt[i] = 0;
}

__global__ void k_count(const int* __restrict__ dst) {
    int e = blockIdx.x * blockDim.x + threadIdx.x;
    if (e < EE) atomicAdd(&g_cnt[dst[e]], 1);
}

// single-block exclusive scan over g_cnt -> g_rowptr / g_cursor / g_invdeg
__global__ void k_scan() {
    __shared__ int s[1024];
    int t = threadIdx.x;
    int running = 0;
    for (int base = 0; base < NN; base += 1024) {
        int i = base + t;
        int v = (i < NN) ? g_cnt[i] : 0;
        s[t] = v;
        __syncthreads();
        for (int off = 1; off < 1024; off <<= 1) {
            int add = (t >= off) ? s[t - off] : 0;
            __syncthreads();
            s[t] += add;
            __syncthreads();
        }
        int excl = s[t] - v;
        if (i < NN) {
            g_rowptr[i] = running + excl;
            g_cursor[i] = running + excl;
            g_invdeg[i] = 1.0f / (float)(v > 1 ? v : 1);
        }
        int total = s[1023];
        __syncthreads();
        running += total;
    }
    if (t == 0) g_rowptr[NN] = running;
}

__global__ void k_fill(const int* __restrict__ src, const int* __restrict__ dst) {
    int e = blockIdx.x * blockDim.x + threadIdx.x;
    if (e < EE) {
        int d = dst[e];
        int p = atomicAdd(&g_cursor[d], 1);
        g_col[p] = src[e];
    }
}

// ---------------- aggregation (warp per node, pure gather) ----------------
// which: 0 -> features from x_ext, 1 -> features from g_h0
__global__ void k_agg(int which, const float* __restrict__ x_ext) {
    int gw = (blockIdx.x * blockDim.x + threadIdx.x) >> 5;
    int lane = threadIdx.x & 31;
    if (gw >= NN) return;
    const float* feat = which ? g_h0 : x_ext;
    int beg = g_rowptr[gw], end = g_rowptr[gw + 1];
    float4 acc = make_float4(0.f, 0.f, 0.f, 0.f);
    for (int e = beg; e < end; ++e) {
        int c = g_col[e];
        float4 v = *(const float4*)&feat[c * DD + lane * 4];
        acc.x += v.x; acc.y += v.y; acc.z += v.z; acc.w += v.w;
    }
    float id = g_invdeg[gw];
    acc.x *= id; acc.y *= id; acc.z *= id; acc.w *= id;
    *(float4*)&g_agg[gw * DD + lane * 4] = acc;
}

// ---------------- fused SAGE layer: h = act(BN(x@Ws + agg@Wn + b)) ----------------
// K = 256 (first 128 from xin, second 128 from g_agg). BM=64, BN=128, BK=16.
__global__ void k_layer(int layer, const float* __restrict__ x_ext,
                        const float* __restrict__ ws, const float* __restrict__ wn,
                        const float* __restrict__ bb, const float* __restrict__ gm,
                        const float* __restrict__ bt, const float* __restrict__ rm,
                        const float* __restrict__ rv) {
    __shared__ float As[16][64];
    __shared__ float Bs[16][128];
    __shared__ float sS[128], sH[128];

    const float* xin = (layer == 0) ? x_ext : g_h0;
    float* hout = (layer == 0) ? g_h0 : g_h1;
    int fix = layer; // nan_to_num only after layer 1

    int tid = threadIdx.x;
    if (tid < 128) {
        float s = gm[tid] * rsqrtf(rv[tid] + 1e-5f);
        sS[tid] = s;
        sH[tid] = (bb[tid] - rm[tid]) * s + bt[tid];
    }

    int tx = tid & 31;        // 32 col groups x 4 cols
    int ty = tid >> 5;        // 8 row groups x 8 rows
    int m0 = blockIdx.x * 64;

    int am = tid & 63, aq = tid >> 6;       // A loader
    int bj = (tid & 31) * 4, bk = tid >> 5; // B loader

    float acc[8][4] = {};

    for (int kc = 0; kc < 16; ++kc) {
        int k0 = kc * 16;
        const float* Asrc = (k0 < 128) ? xin : g_agg;
        const float* Bsrc = (k0 < 128) ? ws : wn;
        int ks = (k0 < 128) ? k0 : (k0 - 128);

        int row = m0 + am;
        float4 av = make_float4(0.f, 0.f, 0.f, 0.f);
        if (row < NN) av = *(const float4*)&Asrc[row * DD + ks + aq * 4];
        As[aq * 4 + 0][am] = av.x;
        As[aq * 4 + 1][am] = av.y;
        As[aq * 4 + 2][am] = av.z;
        As[aq * 4 + 3][am] = av.w;

        *(float4*)&Bs[bk][bj]     = *(const float4*)&Bsrc[(ks + bk) * 128 + bj];
        *(float4*)&Bs[bk + 8][bj] = *(const float4*)&Bsrc[(ks + bk + 8) * 128 + bj];
        __syncthreads();

#pragma unroll
        for (int kk = 0; kk < 16; ++kk) {
            float4 b4 = *(float4*)&Bs[kk][tx * 4];
            float4 a0 = *(float4*)&As[kk][ty * 8];
            float4 a1 = *(float4*)&As[kk][ty * 8 + 4];
            float ar[8] = {a0.x, a0.y, a0.z, a0.w, a1.x, a1.y, a1.z, a1.w};
            float br[4] = {b4.x, b4.y, b4.z, b4.w};
#pragma unroll
            for (int r = 0; r < 8; ++r)
#pragma unroll
                for (int c = 0; c < 4; ++c)
                    acc[r][c] = fmaf(ar[r], br[c], acc[r][c]);
        }
        __syncthreads();
    }

    int j0 = tx * 4;
    float s0 = sS[j0], s1 = sS[j0 + 1], s2 = sS[j0 + 2], s3 = sS[j0 + 3];
    float h0c = sH[j0], h1c = sH[j0 + 1], h2c = sH[j0 + 2], h3c = sH[j0 + 3];
#pragma unroll
    for (int r = 0; r < 8; ++r) {
        int row = m0 + ty * 8 + r;
        if (row < NN) {
            float4 o;
            o.x = postact(acc[r][0] * s0 + h0c, fix);
            o.y = postact(acc[r][1] * s1 + h1c, fix);
            o.z = postact(acc[r][2] * s2 + h2c, fix);
            o.w = postact(acc[r][3] * s3 + h3c, fix);
            *(float4*)&hout[row * DD + j0] = o;
        }
    }
}

// ---------------- fused candidate MLP: 257 -> 64 -> 64 -> 1 ----------------
// BM = 32 candidates per block, 256 threads, static smem (< 48 KB).
__global__ void k_mlp(const int* __restrict__ cu, const int* __restrict__ cv,
                      const float* __restrict__ cfeat,
                      const float* __restrict__ mw0, const float* __restrict__ mb0,
                      const float* __restrict__ mw1, const float* __restrict__ mb1,
                      const float* __restrict__ mw2, const float* __restrict__ mb2,
                      float* __restrict__ yout) {
    __shared__ float ce[32 * 260];   // [cand][257 padded to 260]; reused as z2
    __shared__ float z1[32 * 68];    // [cand][64 padded to 68]
    __shared__ float Bs[16 * 64];
    __shared__ float cst[260];       // mw0 last row | mb0 | mb1 | mw2 | mb2

    const float* h = g_h1;
    int tid = threadIdx.x;
    int c0 = blockIdx.x * 32;

    if (tid < 64) {
        cst[tid]        = mw0[256 * 64 + tid];
        cst[64 + tid]   = mb0[tid];
        cst[128 + tid]  = mb1[tid];
        cst[192 + tid]  = mw2[tid];
    }
    if (tid == 0) cst[256] = mb2[0];

    // stage candidate embeddings
    int wid = tid >> 5, lane = tid & 31;
    for (int r = 0; r < 4; ++r) {
        int cl = wid * 4 + r;
        int c = c0 + cl;
        float4 fu = make_float4(0.f, 0.f, 0.f, 0.f), fv = fu;
        float f1 = 0.f;
        if (c < CC) {
            int u = cu[c], v = cv[c];
            fu = *(const float4*)&h[u * DD + lane * 4];
            fv = *(const float4*)&h[v * DD + lane * 4];
            f1 = cfeat[c];
        }
        *(float4*)&ce[cl * 260 + lane * 4] = fu;
        *(float4*)&ce[cl * 260 + 128 + lane * 4] = fv;
        if (lane == 0) ce[cl * 260 + 256] = f1;
    }
    __syncthreads();

    int tx = tid & 15, ty = tid >> 4; // tx: 16 x 4 cols; ty: 16 x 2 candidates
    int j0 = tx * 4;

    // stage 1: z1 = lrelu(CE @ mw0 + mb0)
    float acc[2][4] = {};
    for (int k0 = 0; k0 < 256; k0 += 16) {
        *(float4*)&Bs[(tid >> 4) * 64 + (tid & 15) * 4] =
            *(const float4*)&mw0[(k0 + (tid >> 4)) * 64 + (tid & 15) * 4];
        __syncthreads();
#pragma unroll
        for (int kk = 0; kk < 16; ++kk) {
            float4 b4 = *(float4*)&Bs[kk * 64 + j0];
            float a0 = ce[(ty * 2) * 260 + k0 + kk];
            float a1 = ce[(ty * 2 + 1) * 260 + k0 + kk];
            acc[0][0] = fmaf(a0, b4.x, acc[0][0]); acc[0][1] = fmaf(a0, b4.y, acc[0][1]);
            acc[0][2] = fmaf(a0, b4.z, acc[0][2]); acc[0][3] = fmaf(a0, b4.w, acc[0][3]);
            acc[1][0] = fmaf(a1, b4.x, acc[1][0]); acc[1][1] = fmaf(a1, b4.y, acc[1][1]);
            acc[1][2] = fmaf(a1, b4.z, acc[1][2]); acc[1][3] = fmaf(a1, b4.w, acc[1][3]);
        }
        __syncthreads();
    }
    { // k = 256 tail term
        float4 b4 = *(float4*)&cst[j0];
        float a0 = ce[(ty * 2) * 260 + 256];
        float a1 = ce[(ty * 2 + 1) * 260 + 256];
        acc[0][0] = fmaf(a0, b4.x, acc[0][0]); acc[0][1] = fmaf(a0, b4.y, acc[0][1]);
        acc[0][2] = fmaf(a0, b4.z, acc[0][2]); acc[0][3] = fmaf(a0, b4.w, acc[0][3]);
        acc[1][0] = fmaf(a1, b4.x, acc[1][0]); acc[1][1] = fmaf(a1, b4.y, acc[1][1]);
        acc[1][2] = fmaf(a1, b4.z, acc[1][2]); acc[1][3] = fmaf(a1, b4.w, acc[1][3]);
    }
#pragma unroll
    for (int i = 0; i < 2; ++i) {
        float4 o;
        o.x = lrelu(acc[i][0] + cst[64 + j0]);
        o.y = lrelu(acc[i][1] + cst[64 + j0 + 1]);
        o.z = lrelu(acc[i][2] + cst[64 + j0 + 2]);
        o.w = lrelu(acc[i][3] + cst[64 + j0 + 3]);
        *(float4*)&z1[(ty * 2 + i) * 68 + j0] = o;
    }
    __syncthreads();

    // stage 2: z2 = lrelu(z1 @ mw1 + mb1)
    float acc2[2][4] = {};
    for (int k0 = 0; k0 < 64; k0 += 16) {
        *(float4*)&Bs[(tid >> 4) * 64 + (tid & 15) * 4] =
            *(const float4*)&mw1[(k0 + (tid >> 4)) * 64 + (tid & 15) * 4];
        __syncthreads();
#pragma unroll
        for (int kk = 0; kk < 16; ++kk) {
            float4 b4 = *(float4*)&Bs[kk * 64 + j0];
            float a0 = z1[(ty * 2) * 68 + k0 + kk];
            float a1 = z1[(ty * 2 + 1) * 68 + k0 + kk];
            acc2[0][0] = fmaf(a0, b4.x, acc2[0][0]); acc2[0][1] = fmaf(a0, b4.y, acc2[0][1]);
            acc2[0][2] = fmaf(a0, b4.z, acc2[0][2]); acc2[0][3] = fmaf(a0, b4.w, acc2[0][3]);
            acc2[1][0] = fmaf(a1, b4.x, acc2[1][0]); acc2[1][1] = fmaf(a1, b4.y, acc2[1][1]);
            acc2[1][2] = fmaf(a1, b4.z, acc2[1][2]); acc2[1][3] = fmaf(a1, b4.w, acc2[1][3]);
        }
        __syncthreads();
    }
    float* z2 = ce; // alias (ce no longer needed)
#pragma unroll
    for (int i = 0; i < 2; ++i) {
        float4 o;
        o.x = lrelu(acc2[i][0] + cst[128 + j0]);
        o.y = lrelu(acc2[i][1] + cst[128 + j0 + 1]);
        o.z = lrelu(acc2[i][2] + cst[128 + j0 + 2]);
        o.w = lrelu(acc2[i][3] + cst[128 + j0 + 3]);
        *(float4*)&z2[(ty * 2 + i) * 68 + j0] = o;
    }
    __syncthreads();

    // stage 3: y = z2 @ mw2 + mb2
    if (tid < 32) {
        int m = tid;
        float a = cst[256];
#pragma unroll
        for (int j = 0; j < 64; ++j) a = fmaf(z2[m * 68 + j], cst[192 + j], a);
        int c = c0 + m;
        if (c < CC) yout[c] = a;
    }
}

// ---------------- softmax over C ----------------
__global__ void k_rinit() { g_umax = 0u; g_sum = 0.f; }

__global__ void k_max(const float* __restrict__ y) {
    float m = -3.402823466e38f;
    for (int i = blockIdx.x * blockDim.x + threadIdx.x; i < CC; i += gridDim.x * blockDim.x)
        m = fmaxf(m, y[i]);
#pragma unroll
    for (int o = 16; o > 0; o >>= 1) m = fmaxf(m, __shfl_xor_sync(0xffffffffu, m, o));
    __shared__ float sb[8];
    if ((threadIdx.x & 31) == 0) sb[threadIdx.x >> 5] = m;
    __syncthreads();
    if (threadIdx.x == 0) {
        float mm = sb[0];
        for (int i = 1; i < 8; ++i) mm = fmaxf(mm, sb[i]);
        atomicMax(&g_umax, fkey(mm));
    }
}

__global__ void k_sum(const float* __restrict__ y) {
    float mx = fdec(g_umax);
    float s = 0.f;
    for (int i = blockIdx.x * blockDim.x + threadIdx.x; i < CC; i += gridDim.x * blockDim.x)
        s += expf(y[i] - mx);
#pragma unroll
    for (int o = 16; o > 0; o >>= 1) s += __shfl_xor_sync(0xffffffffu, s, o);
    __shared__ float sb[8];
    if ((threadIdx.x & 31) == 0) sb[threadIdx.x >> 5] = s;
    __syncthreads();
    if (threadIdx.x == 0) {
        float t = 0.f;
        for (int i = 0; i < 8; ++i) t += sb[i];
        atomicAdd(&g_sum, t);
    }
}

__global__ void k_norm(const float* __restrict__ y, float* __restrict__ outp) {
    int i = blockIdx.x * blockDim.x + threadIdx.x;
    if (i < CC) {
        float mx = fdec(g_umax);
        float inv = 1.f / g_sum;
        outp[i] = expf(y[i] - mx) * inv;
    }
}

// ---------------- launch ----------------
extern "C" void kernel_launch(void* const* d_in, const int* in_sizes, int n_in,
                              void* d_out, int out_size) {
    const float* x   = (const float*)d_in[0];
    const int*   src = (const int*)d_in[1];
    const int*   dst = (const int*)d_in[2];
    const int*   cu  = (const int*)d_in[3];
    const int*   cv  = (const int*)d_in[4];
    const float* cf  = (const float*)d_in[5];

    const float* ws0 = (const float*)d_in[6];
    const float* wn0 = (const float*)d_in[7];
    const float* b0  = (const float*)d_in[8];
    const float* g0  = (const float*)d_in[9];
    const float* be0 = (const float*)d_in[10];
    const float* rm0 = (const float*)d_in[11];
    const float* rv0 = (const float*)d_in[12];

    const float* ws1 = (const float*)d_in[13];
    const float* wn1 = (const float*)d_in[14];
    const float* b1  = (const float*)d_in[15];
    const float* g1  = (const float*)d_in[16];
    const float* be1 = (const float*)d_in[17];
    const float* rm1 = (const float*)d_in[18];
    const float* rv1 = (const float*)d_in[19];

    const float* mw0 = (const float*)d_in[20];
    const float* mb0 = (const float*)d_in[21];
    const float* mw1 = (const float*)d_in[22];
    const float* mb1 = (const float*)d_in[23];
    const float* mw2 = (const float*)d_in[24];
    const float* mb2 = (const float*)d_in[25];

    float* out = (float*)d_out;

    // CSR build (once per launch, reused by both layers)
    k_zero_cnt<<<(NN + 255) / 256, 256>>>();
    k_count<<<(EE + 255) / 256, 256>>>(dst);
    k_scan<<<1, 1024>>>();
    k_fill<<<(EE + 255) / 256, 256>>>(src, dst);

    // layer 0
    k_agg<<<(NN * 32 + 255) / 256, 256>>>(0, x);
    k_layer<<<(NN + 63) / 64, 256>>>(0, x, ws0, wn0, b0, g0, be0, rm0, rv0);

    // layer 1 (+ nan_to_num)
    k_agg<<<(NN * 32 + 255) / 256, 256>>>(1, x);
    k_layer<<<(NN + 63) / 64, 256>>>(1, x, ws1, wn1, b1, g1, be1, rm1, rv1);

    // candidate MLP -> y in out[0:C)
    k_mlp<<<(CC + 31) / 32, 256>>>(cu, cv, cf, mw0, mb0, mw1, mb1, mw2, mb2, out);

    // softmax -> out[C:2C)
    k_rinit<<<1, 1>>>();
    k_max<<<(CC + 255) / 256, 256>>>(out);
    k_sum<<<(CC + 255) / 256, 256>>>(out);
    if (out_size >= 2 * CC)
        k_norm<<<(CC + 255) / 256, 256>>>(out, out + CC);
}

// round 6
// speedup vs baseline: 1.6175x; 1.6175x over previous
#include <cuda_runtime.h>
#include <cuda_bf16.h>
#include <cstdint>
#include <math.h>

#define NN 50000
#define EE 800000
#define CC 100000
#define DD 128

// ============ helpers ============
__device__ __forceinline__ uint32_t s2u(const void* p) {
    uint32_t a; asm("{ .reg .u64 t; cvta.to.shared.u64 t, %1; cvt.u32.u64 %0, t; }" : "=r"(a) : "l"(p)); return a;
}
__device__ __forceinline__ void ldsm4(uint32_t addr, uint32_t r[4]) {
    asm volatile("ldmatrix.sync.aligned.m8n8.x4.shared.b16 {%0,%1,%2,%3}, [%4];"
        : "=r"(r[0]), "=r"(r[1]), "=r"(r[2]), "=r"(r[3]) : "r"(addr));
}
__device__ __forceinline__ void mma16816(float c[4], const uint32_t a[4], const uint32_t b[2]) {
    asm volatile("mma.sync.aligned.m16n8k16.row.col.f32.bf16.bf16.f32 "
        "{%0,%1,%2,%3},{%4,%5,%6,%7},{%8,%9},{%0,%1,%2,%3};"
        : "+f"(c[0]), "+f"(c[1]), "+f"(c[2]), "+f"(c[3])
        : "r"(a[0]), "r"(a[1]), "r"(a[2]), "r"(a[3]), "r"(b[0]), "r"(b[1]));
}
__device__ __forceinline__ uint32_t pack_hl(float a, float b, uint32_t& lo) {
    __nv_bfloat16 ha = __float2bfloat16(a), hb = __float2bfloat16(b);
    __nv_bfloat162 H; H.x = ha; H.y = hb;
    __nv_bfloat162 L; L.x = __float2bfloat16(a - __bfloat162float(ha));
    L.y = __float2bfloat16(b - __bfloat162float(hb));
    lo = reinterpret_cast<uint32_t&>(L);
    return reinterpret_cast<uint32_t&>(H);
}
__device__ __forceinline__ float lrelu(float v) { return v > 0.f ? v : 0.01f * v; }
__device__ __forceinline__ float postact(float v, int fix) {
    v = v > 0.f ? v : 0.01f * v;
    if (fix) { if (isnan(v)) v = 1e-14f; else if (isinf(v)) v = v > 0.f ? 3.402823466e38f : -3.402823466e38f; }
    return v;
}
__device__ __forceinline__ unsigned fkey(float f) { unsigned u = __float_as_uint(f); return (u & 0x80000000u) ? ~u : (u | 0x80000000u); }
__device__ __forceinline__ float fdec(unsigned u) { return (u & 0x80000000u) ? __uint_as_float(u & 0x7fffffffu) : __uint_as_float(~u); }

// ============ scratch ============
static __device__ float g_h0[NN * DD];
static __device__ float g_h1[NN * DD];
static __device__ __nv_bfloat16 g_xhi[NN*DD], g_xlo[NN*DD];
static __device__ __nv_bfloat16 g_h0hi[NN*DD], g_h0lo[NN*DD];
static __device__ __nv_bfloat16 g_aghi[NN*DD], g_aglo[NN*DD];
static __device__ __nv_bfloat16 g_W0hi[128*256], g_W0lo[128*256];
static __device__ __nv_bfloat16 g_W1hi[128*256], g_W1lo[128*256];
static __device__ __nv_bfloat16 g_M0hi[64*256], g_M0lo[64*256];
static __device__ __nv_bfloat16 g_M1hi[64*64], g_M1lo[64*64];
static __device__ int g_rowptr[NN+1], g_cursor[NN], g_cnt[NN], g_col[EE];
static __device__ float g_invdeg[NN];
static __device__ unsigned g_umax;
static __device__ float g_sum;

// ============ CSR ============
__global__ void k_zero_cnt() { int i = blockIdx.x*blockDim.x+threadIdx.x; if (i < NN) g_cnt[i] = 0; }
__global__ void k_count(const int* __restrict__ dst) { int e = blockIdx.x*blockDim.x+threadIdx.x; if (e < EE) atomicAdd(&g_cnt[dst[e]], 1); }
__global__ void k_scan() {
    __shared__ int ws[32]; __shared__ int ctot;
    int t = threadIdx.x, lane = t & 31, w = t >> 5, run = 0;
    for (int base = 0; base < NN; base += 1024) {
        int i = base + t, v = (i < NN) ? g_cnt[i] : 0, x = v;
#pragma unroll
        for (int o = 1; o < 32; o <<= 1) { int y = __shfl_up_sync(~0u, x, o); if (lane >= o) x += y; }
        if (lane == 31) ws[w] = x;
        __syncthreads();
        if (w == 0) {
            int s = ws[lane];
#pragma unroll
            for (int o = 1; o < 32; o <<= 1) { int y = __shfl_up_sync(~0u, s, o); if (lane >= o) s += y; }
            ws[lane] = s; if (lane == 31) ctot = s;
        }
        __syncthreads();
        int excl = x + (w ? ws[w-1] : 0) - v;
        if (i < NN) { g_rowptr[i] = run + excl; g_cursor[i] = run + excl; g_invdeg[i] = 1.0f / (float)(v > 1 ? v : 1); }
        run += ctot;
        __syncthreads();
    }
    if (t == 0) g_rowptr[NN] = run;
}
__global__ void k_fill(const int* __restrict__ src, const int* __restrict__ dst) {
    int e = blockIdx.x*blockDim.x+threadIdx.x;
    if (e < EE) { int p = atomicAdd(&g_cursor[dst[e]], 1); g_col[p] = src[e]; }
}

// ============ conversions ============
__global__ void k_conv_x(const float* __restrict__ x) {
    int i = blockIdx.x*blockDim.x+threadIdx.x;
    if (i < NN*DD) {
        float v = x[i]; __nv_bfloat16 h = __float2bfloat16(v);
        g_xhi[i] = h; g_xlo[i] = __float2bfloat16(v - __bfloat162float(h));
    }
}
__global__ void k_conv_w(const float* __restrict__ ws0, const float* __restrict__ wn0,
                         const float* __restrict__ ws1, const float* __restrict__ wn1,
                         const float* __restrict__ mw0, const float* __restrict__ mw1) {
    int i = blockIdx.x*blockDim.x+threadIdx.x;
    float v; __nv_bfloat16 *ph, *pl; int idx;
    if (i < 32768)      { int n = i>>8, k = i&255; v = (k<128) ? ws0[k*128+n] : wn0[(k-128)*128+n]; ph = g_W0hi; pl = g_W0lo; idx = i; }
    else if (i < 65536) { int j = i-32768, n = j>>8, k = j&255; v = (k<128) ? ws1[k*128+n] : wn1[(k-128)*128+n]; ph = g_W1hi; pl = g_W1lo; idx = j; }
    else if (i < 81920) { int j = i-65536, n = j>>8, k = j&255; v = mw0[k*64+n]; ph = g_M0hi; pl = g_M0lo; idx = j; }
    else if (i < 86016) { int j = i-81920, n = j>>6, k = j&63;  v = mw1[k*64+n]; ph = g_M1hi; pl = g_M1lo; idx = j; }
    else return;
    __nv_bfloat16 h = __float2bfloat16(v);
    ph[idx] = h; pl[idx] = __float2bfloat16(v - __bfloat162float(h));
}

// ============ aggregation -> bf16 hi/lo ============
__global__ void k_agg(int which, const float* __restrict__ x_ext) {
    int gw = (blockIdx.x*blockDim.x+threadIdx.x) >> 5, lane = threadIdx.x & 31;
    if (gw >= NN) return;
    const float* feat = which ? g_h0 : x_ext;
    int beg = g_rowptr[gw], end = g_rowptr[gw+1];
    float4 acc = make_float4(0.f, 0.f, 0.f, 0.f);
    for (int e = beg; e < end; ++e) {
        float4 v = *(const float4*)&feat[g_col[e]*DD + lane*4];
        acc.x += v.x; acc.y += v.y; acc.z += v.z; acc.w += v.w;
    }
    float id = g_invdeg[gw];
    acc.x *= id; acc.y *= id; acc.z *= id; acc.w *= id;
    uint32_t l01, l23, h01 = pack_hl(acc.x, acc.y, l01), h23 = pack_hl(acc.z, acc.w, l23);
    *(uint2*)&g_aghi[gw*DD + lane*4] = make_uint2(h01, h23);
    *(uint2*)&g_aglo[gw*DD + lane*4] = make_uint2(l01, l23);
}

// ============ SAGE layer: HMMA bf16x3, tile 128x128, K=256 in 8 chunks ============
__global__ __launch_bounds__(256) void k_layer_mma(int layer,
        const float* __restrict__ bb, const float* __restrict__ gm,
        const float* __restrict__ bt, const float* __restrict__ rm, const float* __restrict__ rv) {
    __shared__ __align__(16) uint8_t Ah[10240], Al[10240], Bh_[10240], Bl_[10240];
    __shared__ float sS[128], sH[128];
    int tid = threadIdx.x, lane = tid & 31, wid = tid >> 5;
    const __nv_bfloat16 *Axh = layer ? g_h0hi : g_xhi, *Axl = layer ? g_h0lo : g_xlo;
    const __nv_bfloat16 *Wh = layer ? g_W1hi : g_W0hi, *Wl = layer ? g_W1lo : g_W0lo;
    float* hout = layer ? g_h1 : g_h0;
    if (tid < 128) {
        float s = gm[tid] * rsqrtf(rv[tid] + 1e-5f);
        sS[tid] = s; sH[tid] = (bb[tid] - rm[tid]) * s + bt[tid];
    }
    int m0 = blockIdx.x * 128;
    int mwarp = (wid & 3) * 32, nwarp = (wid >> 2) * 64;
    int g = lane >> 3, i = lane & 7;
    int laneA = (i + 8*(g & 1)) * 80 + (g >> 1) * 16;   // bytes, stride 80
    int laneB = (i + 8*(g >> 1)) * 80 + (g & 1) * 16;
    uint32_t aAh = s2u(Ah), aAl = s2u(Al), aBh = s2u(Bh_), aBl = s2u(Bl_);
    float acc[2][8][4] = {};

    for (int c = 0; c < 8; c++) {
        const __nv_bfloat16 *ah, *al; int kbA;
        if (c < 4) { ah = Axh; al = Axl; kbA = c * 32; } else { ah = g_aghi; al = g_aglo; kbA = (c - 4) * 32; }
        int kbB = c * 32;   // weight K offset is GLOBAL k
        __syncthreads();
        for (int it = tid; it < 512; it += 256) {
            int r = it >> 2, q = it & 3;
            int row = m0 + r;
            uint4 vh = make_uint4(0,0,0,0), vl = vh;
            if (row < NN) { vh = *(const uint4*)&ah[row*DD + kbA + q*8]; vl = *(const uint4*)&al[row*DD + kbA + q*8]; }
            *(uint4*)(Ah + r*80 + q*16) = vh;
            *(uint4*)(Al + r*80 + q*16) = vl;
            *(uint4*)(Bh_ + r*80 + q*16) = *(const uint4*)&Wh[r*256 + kbB + q*8];
            *(uint4*)(Bl_ + r*80 + q*16) = *(const uint4*)&Wl[r*256 + kbB + q*8];
        }
        __syncthreads();
#pragma unroll
        for (int ks = 0; ks < 2; ks++) {
            uint32_t a_hi[2][4], a_lo[2][4], b_hi[8][2], b_lo[8][2];
#pragma unroll
            for (int mf = 0; mf < 2; mf++) {
                ldsm4(aAh + laneA + (mwarp + mf*16)*80 + ks*32, a_hi[mf]);
                ldsm4(aAl + laneA + (mwarp + mf*16)*80 + ks*32, a_lo[mf]);
            }
#pragma unroll
            for (int np = 0; np < 4; np++) {
                uint32_t r4[4];
                ldsm4(aBh + laneB + (nwarp + np*16)*80 + ks*32, r4);
                b_hi[np*2][0] = r4[0]; b_hi[np*2][1] = r4[1]; b_hi[np*2+1][0] = r4[2]; b_hi[np*2+1][1] = r4[3];
                ldsm4(aBl + laneB + (nwarp + np*16)*80 + ks*32, r4);
                b_lo[np*2][0] = r4[0]; b_lo[np*2][1] = r4[1]; b_lo[np*2+1][0] = r4[2]; b_lo[np*2+1][1] = r4[3];
            }
#pragma unroll
            for (int mf = 0; mf < 2; mf++)
#pragma unroll
                for (int nf = 0; nf < 8; nf++) {
                    mma16816(acc[mf][nf], a_hi[mf], b_hi[nf]);
                    mma16816(acc[mf][nf], a_lo[mf], b_hi[nf]);
                    mma16816(acc[mf][nf], a_hi[mf], b_lo[nf]);
                }
        }
    }
    int r0 = mwarp + (lane >> 2), cb = nwarp + (lane & 3) * 2;
#pragma unroll
    for (int mf = 0; mf < 2; mf++) {
        int r1 = m0 + r0 + mf*16, r2 = r1 + 8;
#pragma unroll
        for (int nf = 0; nf < 8; nf++) {
            int col = cb + nf * 8;
            float s0 = sS[col], s1 = sS[col+1], h0 = sH[col], h1 = sH[col+1];
            if (r1 < NN) {
                float o0 = postact(acc[mf][nf][0]*s0 + h0, layer);
                float o1 = postact(acc[mf][nf][1]*s1 + h1, layer);
                *(float2*)&hout[r1*DD + col] = make_float2(o0, o1);
                if (!layer) { uint32_t l, h = pack_hl(o0, o1, l); *(uint32_t*)&g_h0hi[r1*DD + col] = h; *(uint32_t*)&g_h0lo[r1*DD + col] = l; }
            }
            if (r2 < NN) {
                float o0 = postact(acc[mf][nf][2]*s0 + h0, layer);
                float o1 = postact(acc[mf][nf][3]*s1 + h1, layer);
                *(float2*)&hout[r2*DD + col] = make_float2(o0, o1);
                if (!layer) { uint32_t l, h = pack_hl(o0, o1, l); *(uint32_t*)&g_h0hi[r2*DD + col] = h; *(uint32_t*)&g_h0lo[r2*DD + col] = l; }
            }
        }
    }
}

// ============ candidate MLP: HMMA bf16x3, 128 cands/block ============
#define SM_MLP 58368
// GEMM1: A1H 0..10240, A1L 10240..20480, B0H 20480..25600, B0L 25600..30720
// z1:    Z1H 0..18432, Z1L 18432..36864 (stride 144)
// B1:    B1H 36864..46080, B1L 46080..55296 (stride 144)
// cst floats @55296; su @56840; sv @57352
__global__ __launch_bounds__(256) void k_mlp_mma(
        const int* __restrict__ cu, const int* __restrict__ cv, const float* __restrict__ cf,
        const float* __restrict__ mw0, const float* __restrict__ mb0,
        const float* __restrict__ mb1, const float* __restrict__ mw2,
        const float* __restrict__ mb2, float* __restrict__ yout) {
    extern __shared__ __align__(16) uint8_t sm[];
    float* cst = (float*)(sm + 55296);
    int* su = (int*)(sm + 56840);
    int* sv = (int*)(sm + 57352);
    int tid = threadIdx.x, lane = tid & 31, wid = tid >> 5;
    int c0 = blockIdx.x * 128;
    int mwarp = (wid & 3) * 32, nwarp = (wid >> 2) * 32;
    int g = lane >> 3, i = lane & 7;
    int laneA  = (i + 8*(g & 1)) * 80 + (g >> 1) * 16;
    int laneB  = (i + 8*(g >> 1)) * 80 + (g & 1) * 16;
    int laneA2 = (i + 8*(g & 1)) * 144 + (g >> 1) * 16;
    int laneB2 = (i + 8*(g >> 1)) * 144 + (g & 1) * 16;
    uint32_t sbase = s2u(sm);

    if (tid < 64) {
        cst[tid]       = mb0[tid];
        cst[64 + tid]  = mw0[256*64 + tid];
        cst[128 + tid] = mb1[tid];
        cst[192 + tid] = mw2[tid];
    }
    if (tid == 0) cst[384] = mb2[0];
    if (tid < 128) {
        int c = c0 + tid;
        su[tid] = (c < CC) ? cu[c] : 0;
        sv[tid] = (c < CC) ? cv[c] : 0;
        cst[256 + tid] = (c < CC) ? cf[c] : 0.f;
    }
    for (int it = tid; it < 512; it += 256) {  // B1 staging (stride 144)
        int r = it >> 3, q = it & 7;
        *(uint4*)(sm + 36864 + r*144 + q*16) = *(const uint4*)&g_M1hi[r*64 + q*8];
        *(uint4*)(sm + 46080 + r*144 + q*16) = *(const uint4*)&g_M1lo[r*64 + q*8];
    }

    // GEMM1: CE[128,256] @ M0T -> z1[128,64]
    float acc[2][4][4] = {};
    for (int c = 0; c < 8; c++) {
        int kbA = (c < 4) ? c * 32 : (c - 4) * 32;  // feature offset within h (u or v half)
        int kbB = c * 32;                           // GLOBAL weight K offset
        const int* sel = (c < 4) ? su : sv;
        __syncthreads();
        for (int it = tid; it < 1024; it += 256) {
            int r = it >> 3, q = it & 7;
            int node = sel[r];
            float4 v = *(const float4*)&g_h1[node*DD + kbA + q*4];
            uint32_t l01, l23, h01 = pack_hl(v.x, v.y, l01), h23 = pack_hl(v.z, v.w, l23);
            *(uint2*)(sm + 0     + r*80 + q*8) = make_uint2(h01, h23);
            *(uint2*)(sm + 10240 + r*80 + q*8) = make_uint2(l01, l23);
            if (it < 256) {
                int rr = it >> 2, qq = it & 3;
                *(uint4*)(sm + 20480 + rr*80 + qq*16) = *(const uint4*)&g_M0hi[rr*256 + kbB + qq*8];
                *(uint4*)(sm + 25600 + rr*80 + qq*16) = *(const uint4*)&g_M0lo[rr*256 + kbB + qq*8];
            }
        }
        __syncthreads();
#pragma unroll
        for (int ks = 0; ks < 2; ks++) {
            uint32_t a_hi[2][4], a_lo[2][4], b_hi[4][2], b_lo[4][2];
#pragma unroll
            for (int mf = 0; mf < 2; mf++) {
                ldsm4(sbase + 0     + laneA + (mwarp + mf*16)*80 + ks*32, a_hi[mf]);
                ldsm4(sbase + 10240 + laneA + (mwarp + mf*16)*80 + ks*32, a_lo[mf]);
            }
#pragma unroll
            for (int np = 0; np < 2; np++) {
                uint32_t r4[4];
                ldsm4(sbase + 20480 + laneB + (nwarp + np*16)*80 + ks*32, r4);
                b_hi[np*2][0] = r4[0]; b_hi[np*2][1] = r4[1]; b_hi[np*2+1][0] = r4[2]; b_hi[np*2+1][1] = r4[3];
                ldsm4(sbase + 25600 + laneB + (nwarp + np*16)*80 + ks*32, r4);
                b_lo[np*2][0] = r4[0]; b_lo[np*2][1] = r4[1]; b_lo[np*2+1][0] = r4[2]; b_lo[np*2+1][1] = r4[3];
            }
#pragma unroll
            for (int mf = 0; mf < 2; mf++)
#pragma unroll
                for (int nf = 0; nf < 4; nf++) {
                    mma16816(acc[mf][nf], a_hi[mf], b_hi[nf]);
                    mma16816(acc[mf][nf], a_lo[mf], b_hi[nf]);
                    mma16816(acc[mf][nf], a_hi[mf], b_lo[nf]);
                }
        }
    }
    __syncthreads();  // done with A1/B0 regions before z1 overwrite
    {
        int r0 = mwarp + (lane >> 2), cb = nwarp + (lane & 3) * 2;
#pragma unroll
        for (int mf = 0; mf < 2; mf++) {
            int r1 = r0 + mf*16, r2 = r1 + 8;
            float fz1 = cst[256 + r1], fz2 = cst[256 + r2];
#pragma unroll
            for (int nf = 0; nf < 4; nf++) {
                int col = cb + nf * 8;
                float b0v = cst[col], b1v = cst[col+1], w0 = cst[64+col], w1 = cst[64+col+1];
                float z0 = lrelu(acc[mf][nf][0] + b0v + fz1 * w0);
                float z1 = lrelu(acc[mf][nf][1] + b1v + fz1 * w1);
                uint32_t l, h = pack_hl(z0, z1, l);
                *(uint32_t*)(sm + 0     + r1*144 + col*2) = h;
                *(uint32_t*)(sm + 18432 + r1*144 + col*2) = l;
                z0 = lrelu(acc[mf][nf][2] + b0v + fz2 * w0);
                z1 = lrelu(acc[mf][nf][3] + b1v + fz2 * w1);
                h = pack_hl(z0, z1, l);
                *(uint32_t*)(sm + 0     + r2*144 + col*2) = h;
                *(uint32_t*)(sm + 18432 + r2*144 + col*2) = l;
            }
        }
    }
    __syncthreads();

    // GEMM2: z1[128,64] @ M1T -> z2[128,64]
    float acc2[2][4][4] = {};
#pragma unroll
    for (int ks = 0; ks < 4; ks++) {
        uint32_t a_hi[2][4], a_lo[2][4], b_hi[4][2], b_lo[4][2];
#pragma unroll
        for (int mf = 0; mf < 2; mf++) {
            ldsm4(sbase + 0     + laneA2 + (mwarp + mf*16)*144 + ks*32, a_hi[mf]);
            ldsm4(sbase + 18432 + laneA2 + (mwarp + mf*16)*144 + ks*32, a_lo[mf]);
        }
#pragma unroll
        for (int np = 0; np < 2; np++) {
            uint32_t r4[4];
            ldsm4(sbase + 36864 + laneB2 + (nwarp + np*16)*144 + ks*32, r4);
            b_hi[np*2][0] = r4[0]; b_hi[np*2][1] = r4[1]; b_hi[np*2+1][0] = r4[2]; b_hi[np*2+1][1] = r4[3];
            ldsm4(sbase + 46080 + laneB2 + (nwarp + np*16)*144 + ks*32, r4);
            b_lo[np*2][0] = r4[0]; b_lo[np*2][1] = r4[1]; b_lo[np*2+1][0] = r4[2]; b_lo[np*2+1][1] = r4[3];
        }
#pragma unroll
        for (int mf = 0; mf < 2; mf++)
#pragma unroll
            for (int nf = 0; nf < 4; nf++) {
                mma16816(acc2[mf][nf], a_hi[mf], b_hi[nf]);
                mma16816(acc2[mf][nf], a_lo[mf], b_hi[nf]);
                mma16816(acc2[mf][nf], a_hi[mf], b_lo[nf]);
            }
    }
    // z2 -> regs -> smem floats (stride 68) -> final dot
    float z2r[2][4][4];
    {
        int cb = nwarp + (lane & 3) * 2;
#pragma unroll
        for (int mf = 0; mf < 2; mf++)
#pragma unroll
            for (int nf = 0; nf < 4; nf++) {
                int col = cb + nf * 8;
                z2r[mf][nf][0] = lrelu(acc2[mf][nf][0] + cst[128+col]);
                z2r[mf][nf][1] = lrelu(acc2[mf][nf][1] + cst[128+col+1]);
                z2r[mf][nf][2] = lrelu(acc2[mf][nf][2] + cst[128+col]);
                z2r[mf][nf][3] = lrelu(acc2[mf][nf][3] + cst[128+col+1]);
            }
    }
    __syncthreads();
    float* z2f = (float*)sm;
    {
        int r0 = mwarp + (lane >> 2), cb = nwarp + (lane & 3) * 2;
#pragma unroll
        for (int mf = 0; mf < 2; mf++) {
            int r1 = r0 + mf*16, r2 = r1 + 8;
#pragma unroll
            for (int nf = 0; nf < 4; nf++) {
                int col = cb + nf * 8;
                *(float2*)&z2f[r1*68 + col] = make_float2(z2r[mf][nf][0], z2r[mf][nf][1]);
                *(float2*)&z2f[r2*68 + col] = make_float2(z2r[mf][nf][2], z2r[mf][nf][3]);
            }
        }
    }
    __syncthreads();
    {
        int cand = tid >> 1, half = tid & 1;
        float s = 0.f;
        const float* zr = &z2f[cand*68 + half*32];
        const float* wr = &cst[192 + half*32];
#pragma unroll
        for (int j = 0; j < 32; j++) s = fmaf(zr[j], wr[j], s);
        float other = __shfl_xor_sync(~0u, s, 1);
        if (half == 0) {
            int c = c0 + cand;
            if (c < CC) yout[c] = s + other + cst[384];
        }
    }
}

// ============ softmax ============
__global__ void k_rinit() { g_umax = 0u; g_sum = 0.f; }
__global__ void k_max(const float* __restrict__ y) {
    float m = -3.402823466e38f;
    for (int i = blockIdx.x*blockDim.x+threadIdx.x; i < CC; i += gridDim.x*blockDim.x) m = fmaxf(m, y[i]);
#pragma unroll
    for (int o = 16; o > 0; o >>= 1) m = fmaxf(m, __shfl_xor_sync(~0u, m, o));
    __shared__ float sbuf[8];
    if ((threadIdx.x & 31) == 0) sbuf[threadIdx.x >> 5] = m;
    __syncthreads();
    if (threadIdx.x == 0) { float mm = sbuf[0]; for (int i = 1; i < 8; i++) mm = fmaxf(mm, sbuf[i]); atomicMax(&g_umax, fkey(mm)); }
}
__global__ void k_sum(const float* __restrict__ y) {
    float mx = fdec(g_umax), s = 0.f;
    for (int i = blockIdx.x*blockDim.x+threadIdx.x; i < CC; i += gridDim.x*blockDim.x) s += expf(y[i] - mx);
#pragma unroll
    for (int o = 16; o > 0; o >>= 1) s += __shfl_xor_sync(~0u, s, o);
    __shared__ float sbuf[8];
    if ((threadIdx.x & 31) == 0) sbuf[threadIdx.x >> 5] = s;
    __syncthreads();
    if (threadIdx.x == 0) { float t = 0.f; for (int i = 0; i < 8; i++) t += sbuf[i]; atomicAdd(&g_sum, t); }
}
__global__ void k_norm(const float* __restrict__ y, float* __restrict__ outp) {
    int i = blockIdx.x*blockDim.x+threadIdx.x;
    if (i < CC) outp[i] = expf(y[i] - fdec(g_umax)) * (1.f / g_sum);
}

// ============ launch ============
extern "C" void kernel_launch(void* const* d_in, const int* in_sizes, int n_in,
                              void* d_out, int out_size) {
    const float* x = (const float*)d_in[0];
    const int *src = (const int*)d_in[1], *dst = (const int*)d_in[2];
    const int *cu = (const int*)d_in[3], *cv = (const int*)d_in[4];
    const float* cf = (const float*)d_in[5];
    const float *ws0=(const float*)d_in[6], *wn0=(const float*)d_in[7], *b0=(const float*)d_in[8],
                *g0=(const float*)d_in[9], *be0=(const float*)d_in[10], *rm0=(const float*)d_in[11], *rv0=(const float*)d_in[12];
    const float *ws1=(const float*)d_in[13], *wn1=(const float*)d_in[14], *b1=(const float*)d_in[15],
                *g1=(const float*)d_in[16], *be1=(const float*)d_in[17], *rm1=(const float*)d_in[18], *rv1=(const float*)d_in[19];
    const float *mw0=(const float*)d_in[20], *mb0=(const float*)d_in[21], *mw1=(const float*)d_in[22],
                *mb1=(const float*)d_in[23], *mw2=(const float*)d_in[24], *mb2=(const float*)d_in[25];
    float* out = (float*)d_out;

    static bool attr_done = false;
    if (!attr_done) {
        cudaFuncSetAttribute(k_mlp_mma, cudaFuncAttributeMaxDynamicSharedMemorySize, SM_MLP);
        attr_done = true;
    }

    k_zero_cnt<<<(NN+255)/256, 256>>>();
    k_count<<<(EE+255)/256, 256>>>(dst);
    k_conv_x<<<(NN*DD+255)/256, 256>>>(x);
    k_conv_w<<<(86016+255)/256, 256>>>(ws0, wn0, ws1, wn1, mw0, mw1);
    k_scan<<<1, 1024>>>();
    k_fill<<<(EE+255)/256, 256>>>(src, dst);

    k_agg<<<(NN*32+255)/256, 256>>>(0, x);
    k_layer_mma<<<(NN+127)/128, 256>>>(0, b0, g0, be0, rm0, rv0);
    k_agg<<<(NN*32+255)/256, 256>>>(1, x);
    k_layer_mma<<<(NN+127)/128, 256>>>(1, b1, g1, be1, rm1, rv1);

    k_mlp_mma<<<(CC+127)/128, 256, SM_MLP>>>(cu, cv, cf, mw0, mb0, mb1, mw2, mb2, out);

    k_rinit<<<1, 1>>>();
    k_max<<<(CC+255)/256, 256>>>(out);
    k_sum<<<(CC+255)/256, 256>>>(out);
    if (out_size >= 2*CC) k_norm<<<(CC+255)/256, 256>>>(out, out + CC);
}

// round 9
// speedup vs baseline: 1.8571x; 1.1482x over previous
#include <cuda_runtime.h>
#include <cuda_bf16.h>
#include <cstdint>
#include <math.h>

#define NN 50000
#define EE 800000
#define CC 100000
#define DD 128

// ============ helpers ============
__device__ __forceinline__ uint32_t s2u(const void* p) {
    uint32_t a; asm("{ .reg .u64 t; cvta.to.shared.u64 t, %1; cvt.u32.u64 %0, t; }" : "=r"(a) : "l"(p)); return a;
}
__device__ __forceinline__ void ldsm4(uint32_t addr, uint32_t r[4]) {
    asm volatile("ldmatrix.sync.aligned.m8n8.x4.shared.b16 {%0,%1,%2,%3}, [%4];"
        : "=r"(r[0]), "=r"(r[1]), "=r"(r[2]), "=r"(r[3]) : "r"(addr));
}
__device__ __forceinline__ void mma16816(float c[4], const uint32_t a[4], const uint32_t b[2]) {
    asm volatile("mma.sync.aligned.m16n8k16.row.col.f32.bf16.bf16.f32 "
        "{%0,%1,%2,%3},{%4,%5,%6,%7},{%8,%9},{%0,%1,%2,%3};"
        : "+f"(c[0]), "+f"(c[1]), "+f"(c[2]), "+f"(c[3])
        : "r"(a[0]), "r"(a[1]), "r"(a[2]), "r"(a[3]), "r"(b[0]), "r"(b[1]));
}
__device__ __forceinline__ void cpa16(uint32_t dst, const void* src, int sz) {
    asm volatile("cp.async.cg.shared.global [%0], [%1], 16, %2;" :: "r"(dst), "l"(src), "r"(sz) : "memory");
}
#define CP_COMMIT() asm volatile("cp.async.commit_group;" ::: "memory")
#define CP_WAIT0()  asm volatile("cp.async.wait_group 0;" ::: "memory")
__device__ __forceinline__ uint32_t pack_hl(float a, float b, uint32_t& lo) {
    __nv_bfloat16 ha = __float2bfloat16(a), hb = __float2bfloat16(b);
    __nv_bfloat162 H; H.x = ha; H.y = hb;
    __nv_bfloat162 L; L.x = __float2bfloat16(a - __bfloat162float(ha));
    L.y = __float2bfloat16(b - __bfloat162float(hb));
    lo = reinterpret_cast<uint32_t&>(L);
    return reinterpret_cast<uint32_t&>(H);
}
__device__ __forceinline__ float lrelu(float v) { return v > 0.f ? v : 0.01f * v; }
__device__ __forceinline__ float postact(float v, int fix) {
    v = v > 0.f ? v : 0.01f * v;
    if (fix) { if (isnan(v)) v = 1e-14f; else if (isinf(v)) v = v > 0.f ? 3.402823466e38f : -3.402823466e38f; }
    return v;
}
__device__ __forceinline__ unsigned fkey(float f) { unsigned u = __float_as_uint(f); return (u & 0x80000000u) ? ~u : (u | 0x80000000u); }
__device__ __forceinline__ float fdec(unsigned u) { return (u & 0x80000000u) ? __uint_as_float(u & 0x7fffffffu) : __uint_as_float(~u); }

// ============ scratch ============
static __device__ float g_h0[NN * DD];
static __device__ float g_h1[NN * DD];
static __device__ __nv_bfloat16 g_xhi[NN*DD], g_xlo[NN*DD];
static __device__ __nv_bfloat16 g_h0hi[NN*DD], g_h0lo[NN*DD];
static __device__ __nv_bfloat16 g_aghi[NN*DD], g_aglo[NN*DD];
static __device__ __nv_bfloat16 g_W0hi[128*256], g_W0lo[128*256];
static __device__ __nv_bfloat16 g_W1hi[128*256], g_W1lo[128*256];
static __device__ __nv_bfloat16 g_M0hi[64*256], g_M0lo[64*256];
static __device__ __nv_bfloat16 g_M1hi[64*64], g_M1lo[64*64];
static __device__ int g_rowptr[NN+1], g_cursor[NN], g_cnt[NN], g_col[EE];
static __device__ float g_invdeg[NN];
static __device__ unsigned g_umax;
static __device__ float g_sum;

// ============ fused prep: reset + conv_x + conv_w + softmax-state init ============
__global__ void k_prep(const float* __restrict__ x,
                       const float* __restrict__ ws0, const float* __restrict__ wn0,
                       const float* __restrict__ ws1, const float* __restrict__ wn1,
                       const float* __restrict__ mw0, const float* __restrict__ mw1) {
    int i = blockIdx.x*blockDim.x + threadIdx.x;
    if (i == 0) { g_umax = 0u; g_sum = 0.f; }
    if (i < NN) g_cnt[i] = 0;
    if (i < NN*DD) {
        float v = x[i]; __nv_bfloat16 h = __float2bfloat16(v);
        g_xhi[i] = h; g_xlo[i] = __float2bfloat16(v - __bfloat162float(h));
    }
    if (i < 86016) {
        float v; __nv_bfloat16 *ph, *pl; int idx;
        if (i < 32768)      { int n = i>>8, k = i&255; v = (k<128) ? ws0[k*128+n] : wn0[(k-128)*128+n]; ph = g_W0hi; pl = g_W0lo; idx = i; }
        else if (i < 65536) { int j = i-32768, n = j>>8, k = j&255; v = (k<128) ? ws1[k*128+n] : wn1[(k-128)*128+n]; ph = g_W1hi; pl = g_W1lo; idx = j; }
        else if (i < 81920) { int j = i-65536, n = j>>8, k = j&255; v = mw0[k*64+n]; ph = g_M0hi; pl = g_M0lo; idx = j; }
        else                { int j = i-81920, n = j>>6, k = j&63;  v = mw1[k*64+n]; ph = g_M1hi; pl = g_M1lo; idx = j; }
        __nv_bfloat16 h = __float2bfloat16(v);
        ph[idx] = h; pl[idx] = __float2bfloat16(v - __bfloat162float(h));
    }
}

// ============ CSR ============
__global__ void k_count(const int* __restrict__ dst) { int e = blockIdx.x*blockDim.x+threadIdx.x; if (e < EE) atomicAdd(&g_cnt[dst[e]], 1); }
__global__ void k_scan() {
    __shared__ int ws[32]; __shared__ int ctot;
    int t = threadIdx.x, lane = t & 31, w = t >> 5, run = 0;
    for (int base = 0; base < NN; base += 1024) {
        int i = base + t, v = (i < NN) ? g_cnt[i] : 0, x = v;
#pragma unroll
        for (int o = 1; o < 32; o <<= 1) { int y = __shfl_up_sync(~0u, x, o); if (lane >= o) x += y; }
        if (lane == 31) ws[w] = x;
        __syncthreads();
        if (w == 0) {
            int s = ws[lane];
#pragma unroll
            for (int o = 1; o < 32; o <<= 1) { int y = __shfl_up_sync(~0u, s, o); if (lane >= o) s += y; }
            ws[lane] = s; if (lane == 31) ctot = s;
        }
        __syncthreads();
        int excl = x + (w ? ws[w-1] : 0) - v;
        if (i < NN) { g_rowptr[i] = run + excl; g_cursor[i] = run + excl; g_invdeg[i] = 1.0f / (float)(v > 1 ? v : 1); }
        run += ctot;
        __syncthreads();
    }
    if (t == 0) g_rowptr[NN] = run;
}
__global__ void k_fill(const int* __restrict__ src, const int* __restrict__ dst) {
    int e = blockIdx.x*blockDim.x+threadIdx.x;
    if (e < EE) { int p = atomicAdd(&g_cursor[dst[e]], 1); g_col[p] = src[e]; }
}

// ============ aggregation -> bf16 hi/lo ============
__global__ void k_agg(int which, const float* __restrict__ x_ext) {
    int gw = (blockIdx.x*blockDim.x+threadIdx.x) >> 5, lane = threadIdx.x & 31;
    if (gw >= NN) return;
    const float* feat = which ? g_h0 : x_ext;
    int beg = g_rowptr[gw], end = g_rowptr[gw+1];
    float4 acc = make_float4(0.f, 0.f, 0.f, 0.f);
    for (int e = beg; e < end; ++e) {
        float4 v = *(const float4*)&feat[g_col[e]*DD + lane*4];
        acc.x += v.x; acc.y += v.y; acc.z += v.z; acc.w += v.w;
    }
    float id = g_invdeg[gw];
    acc.x *= id; acc.y *= id; acc.z *= id; acc.w *= id;
    uint32_t l01, l23, h01 = pack_hl(acc.x, acc.y, l01), h23 = pack_hl(acc.z, acc.w, l23);
    *(uint2*)&g_aghi[gw*DD + lane*4] = make_uint2(h01, h23);
    *(uint2*)&g_aglo[gw*DD + lane*4] = make_uint2(l01, l23);
}

// ============ SAGE layer: HMMA bf16x3, tile 128x128, K=256, cp.async double-buffer ============
#define SM_LAYER_DB 81920   // 2 buffers x (Ah|Al|Bh|Bl) x 10240
__global__ __launch_bounds__(256) void k_layer_mma(int layer,
        const float* __restrict__ bb, const float* __restrict__ gm,
        const float* __restrict__ bt, const float* __restrict__ rm, const float* __restrict__ rv) {
    extern __shared__ __align__(16) uint8_t smdyn[];
    __shared__ float sS[128], sH[128];
    int tid = threadIdx.x, lane = tid & 31, wid = tid >> 5;
    const __nv_bfloat16 *Axh = layer ? g_h0hi : g_xhi, *Axl = layer ? g_h0lo : g_xlo;
    const __nv_bfloat16 *Wh = layer ? g_W1hi : g_W0hi, *Wl = layer ? g_W1lo : g_W0lo;
    float* hout = layer ? g_h1 : g_h0;
    if (tid < 128) {
        float s = gm[tid] * rsqrtf(rv[tid] + 1e-5f);
        sS[tid] = s; sH[tid] = (bb[tid] - rm[tid]) * s + bt[tid];
    }
    int m0 = blockIdx.x * 128;
    int mwarp = (wid & 3) * 32, nwarp = (wid >> 2) * 64;
    int g = lane >> 3, i = lane & 7;
    int laneA = (i + 8*(g & 1)) * 80 + (g >> 1) * 16;   // bytes, stride 80
    int laneB = (i + 8*(g >> 1)) * 80 + (g & 1) * 16;
    uint32_t sdyn = s2u(smdyn);
    float acc[2][8][4] = {};

    auto stage = [&](int c) {
        uint32_t buf = sdyn + (uint32_t)(c & 1) * 40960u;
        const __nv_bfloat16 *ah, *al; int kbA;
        if (c < 4) { ah = Axh; al = Axl; kbA = c * 32; } else { ah = g_aghi; al = g_aglo; kbA = (c - 4) * 32; }
        int kbB = c * 32;   // weight K offset is GLOBAL k
        for (int it = tid; it < 512; it += 256) {
            int r = it >> 2, q = it & 3;
            int row = m0 + r;
            int rc = row < NN ? row : 0;
            int sz = row < NN ? 16 : 0;
            uint32_t so = (uint32_t)(r * 80 + q * 16);
            cpa16(buf + so,          &ah[rc*DD + kbA + q*8], sz);
            cpa16(buf + 10240 + so,  &al[rc*DD + kbA + q*8], sz);
            cpa16(buf + 20480 + so,  &Wh[r*256 + kbB + q*8], 16);
            cpa16(buf + 30720 + so,  &Wl[r*256 + kbB + q*8], 16);
        }
        CP_COMMIT();
    };

    stage(0);
    for (int c = 0; c < 8; c++) {
        CP_WAIT0();
        __syncthreads();
        if (c < 7) stage(c + 1);
        uint32_t buf = sdyn + (uint32_t)(c & 1) * 40960u;
        uint32_t aAh = buf, aAl = buf + 10240, aBh = buf + 20480, aBl = buf + 30720;
#pragma unroll
        for (int ks = 0; ks < 2; ks++) {
            uint32_t a_hi[2][4], a_lo[2][4], b_hi[8][2], b_lo[8][2];
#pragma unroll
            for (int mf = 0; mf < 2; mf++) {
                ldsm4(aAh + laneA + (mwarp + mf*16)*80 + ks*32, a_hi[mf]);
                ldsm4(aAl + laneA + (mwarp + mf*16)*80 + ks*32, a_lo[mf]);
            }
#pragma unroll
            for (int np = 0; np < 4; np++) {
                uint32_t r4[4];
                ldsm4(aBh + laneB + (nwarp + np*16)*80 + ks*32, r4);
                b_hi[np*2][0] = r4[0]; b_hi[np*2][1] = r4[1]; b_hi[np*2+1][0] = r4[2]; b_hi[np*2+1][1] = r4[3];
                ldsm4(aBl + laneB + (nwarp + np*16)*80 + ks*32, r4);
                b_lo[np*2][0] = r4[0]; b_lo[np*2][1] = r4[1]; b_lo[np*2+1][0] = r4[2]; b_lo[np*2+1][1] = r4[3];
            }
#pragma unroll
            for (int mf = 0; mf < 2; mf++)
#pragma unroll
                for (int nf = 0; nf < 8; nf++) {
                    mma16816(acc[mf][nf], a_hi[mf], b_hi[nf]);
                    mma16816(acc[mf][nf], a_lo[mf], b_hi[nf]);
                    mma16816(acc[mf][nf], a_hi[mf], b_lo[nf]);
                }
        }
        __syncthreads();
    }
    int r0 = mwarp + (lane >> 2), cb = nwarp + (lane & 3) * 2;
#pragma unroll
    for (int mf = 0; mf < 2; mf++) {
        int r1 = m0 + r0 + mf*16, r2 = r1 + 8;
#pragma unroll
        for (int nf = 0; nf < 8; nf++) {
            int col = cb + nf * 8;
            float s0 = sS[col], s1 = sS[col+1], h0 = sH[col], h1 = sH[col+1];
            if (r1 < NN) {
                float o0 = postact(acc[mf][nf][0]*s0 + h0, layer);
                float o1 = postact(acc[mf][nf][1]*s1 + h1, layer);
                *(float2*)&hout[r1*DD + col] = make_float2(o0, o1);
                if (!layer) { uint32_t l, h = pack_hl(o0, o1, l); *(uint32_t*)&g_h0hi[r1*DD + col] = h; *(uint32_t*)&g_h0lo[r1*DD + col] = l; }
            }
            if (r2 < NN) {
                float o0 = postact(acc[mf][nf][2]*s0 + h0, layer);
                float o1 = postact(acc[mf][nf][3]*s1 + h1, layer);
                *(float2*)&hout[r2*DD + col] = make_float2(o0, o1);
                if (!layer) { uint32_t l, h = pack_hl(o0, o1, l); *(uint32_t*)&g_h0hi[r2*DD + col] = h; *(uint32_t*)&g_h0lo[r2*DD + col] = l; }
            }
        }
    }
}

// ============ candidate MLP: HMMA bf16x3, 128 cands/block ============
#define SM_MLP 58368
// GEMM1: A1H 0..10240, A1L 10240..20480, B0H 20480..25600, B0L 25600..30720
// z1:    Z1H 0..18432, Z1L 18432..36864 (stride 144)
// B1:    B1H 36864..46080, B1L 46080..55296 (stride 144)
// cst floats @55296; su @56840; sv @57352
__global__ __launch_bounds__(256) void k_mlp_mma(
        const int* __restrict__ cu, const int* __restrict__ cv, const float* __restrict__ cf,
        const float* __restrict__ mw0, const float* __restrict__ mb0,
        const float* __restrict__ mb1, const float* __restrict__ mw2,
        const float* __restrict__ mb2, float* __restrict__ yout) {
    extern __shared__ __align__(16) uint8_t sm[];
    float* cst = (float*)(sm + 55296);
    int* su = (int*)(sm + 56840);
    int* sv = (int*)(sm + 57352);
    int tid = threadIdx.x, lane = tid & 31, wid = tid >> 5;
    int c0 = blockIdx.x * 128;
    int mwarp = (wid & 3) * 32, nwarp = (wid >> 2) * 32;
    int g = lane >> 3, i = lane & 7;
    int laneA  = (i + 8*(g & 1)) * 80 + (g >> 1) * 16;
    int laneB  = (i + 8*(g >> 1)) * 80 + (g & 1) * 16;
    int laneA2 = (i + 8*(g & 1)) * 144 + (g >> 1) * 16;
    int laneB2 = (i + 8*(g >> 1)) * 144 + (g & 1) * 16;
    uint32_t sbase = s2u(sm);

    if (tid < 64) {
        cst[tid]       = mb0[tid];
        cst[64 + tid]  = mw0[256*64 + tid];
        cst[128 + tid] = mb1[tid];
        cst[192 + tid] = mw2[tid];
    }
    if (tid == 0) cst[384] = mb2[0];
    if (tid < 128) {
        int c = c0 + tid;
        su[tid] = (c < CC) ? cu[c] : 0;
        sv[tid] = (c < CC) ? cv[c] : 0;
        cst[256 + tid] = (c < CC) ? cf[c] : 0.f;
    }
    for (int it = tid; it < 512; it += 256) {  // B1 staging (stride 144)
        int r = it >> 3, q = it & 7;
        *(uint4*)(sm + 36864 + r*144 + q*16) = *(const uint4*)&g_M1hi[r*64 + q*8];
        *(uint4*)(sm + 46080 + r*144 + q*16) = *(const uint4*)&g_M1lo[r*64 + q*8];
    }

    // GEMM1: CE[128,256] @ M0T -> z1[128,64]
    float acc[2][4][4] = {};
    for (int c = 0; c < 8; c++) {
        int kbA = (c < 4) ? c * 32 : (c - 4) * 32;  // feature offset within h (u or v half)
        int kbB = c * 32;                           // GLOBAL weight K offset
        const int* sel = (c < 4) ? su : sv;
        __syncthreads();
        for (int it = tid; it < 1024; it += 256) {
            int r = it >> 3, q = it & 7;
            int node = sel[r];
            float4 v = *(const float4*)&g_h1[node*DD + kbA + q*4];
            uint32_t l01, l23, h01 = pack_hl(v.x, v.y, l01), h23 = pack_hl(v.z, v.w, l23);
            *(uint2*)(sm + 0     + r*80 + q*8) = make_uint2(h01, h23);
            *(uint2*)(sm + 10240 + r*80 + q*8) = make_uint2(l01, l23);
            if (it < 256) {
                int rr = it >> 2, qq = it & 3;
                *(uint4*)(sm + 20480 + rr*80 + qq*16) = *(const uint4*)&g_M0hi[rr*256 + kbB + qq*8];
                *(uint4*)(sm + 25600 + rr*80 + qq*16) = *(const uint4*)&g_M0lo[rr*256 + kbB + qq*8];
            }
        }
        __syncthreads();
#pragma unroll
        for (int ks = 0; ks < 2; ks++) {
            uint32_t a_hi[2][4], a_lo[2][4], b_hi[4][2], b_lo[4][2];
#pragma unroll
            for (int mf = 0; mf < 2; mf++) {
                ldsm4(sbase + 0     + laneA + (mwarp + mf*16)*80 + ks*32, a_hi[mf]);
                ldsm4(sbase + 10240 + laneA + (mwarp + mf*16)*80 + ks*32, a_lo[mf]);
            }
#pragma unroll
            for (int np = 0; np < 2; np++) {
                uint32_t r4[4];
                ldsm4(sbase + 20480 + laneB + (nwarp + np*16)*80 + ks*32, r4);
                b_hi[np*2][0] = r4[0]; b_hi[np*2][1] = r4[1]; b_hi[np*2+1][0] = r4[2]; b_hi[np*2+1][1] = r4[3];
                ldsm4(sbase + 25600 + laneB + (nwarp + np*16)*80 + ks*32, r4);
                b_lo[np*2][0] = r4[0]; b_lo[np*2][1] = r4[1]; b_lo[np*2+1][0] = r4[2]; b_lo[np*2+1][1] = r4[3];
            }
#pragma unroll
            for (int mf = 0; mf < 2; mf++)
#pragma unroll
                for (int nf = 0; nf < 4; nf++) {
                    mma16816(acc[mf][nf], a_hi[mf], b_hi[nf]);
                    mma16816(acc[mf][nf], a_lo[mf], b_hi[nf]);
                    mma16816(acc[mf][nf], a_hi[mf], b_lo[nf]);
                }
        }
    }
    __syncthreads();  // done with A1/B0 regions before z1 overwrite
    {
        int r0 = mwarp + (lane >> 2), cb = nwarp + (lane & 3) * 2;
#pragma unroll
        for (int mf = 0; mf < 2; mf++) {
            int r1 = r0 + mf*16, r2 = r1 + 8;
            float fz1 = cst[256 + r1], fz2 = cst[256 + r2];
#pragma unroll
            for (int nf = 0; nf < 4; nf++) {
                int col = cb + nf * 8;
                float b0v = cst[col], b1v = cst[col+1], w0 = cst[64+col], w1 = cst[64+col+1];
                float z0 = lrelu(acc[mf][nf][0] + b0v + fz1 * w0);
                float z1 = lrelu(acc[mf][nf][1] + b1v + fz1 * w1);
                uint32_t l, h = pack_hl(z0, z1, l);
                *(uint32_t*)(sm + 0     + r1*144 + col*2) = h;
                *(uint32_t*)(sm + 18432 + r1*144 + col*2) = l;
                z0 = lrelu(acc[mf][nf][2] + b0v + fz2 * w0);
                z1 = lrelu(acc[mf][nf][3] + b1v + fz2 * w1);
                h = pack_hl(z0, z1, l);
                *(uint32_t*)(sm + 0     + r2*144 + col*2) = h;
                *(uint32_t*)(sm + 18432 + r2*144 + col*2) = l;
            }
        }
    }
    __syncthreads();

    // GEMM2: z1[128,64] @ M1T -> z2[128,64]
    float acc2[2][4][4] = {};
#pragma unroll
    for (int ks = 0; ks < 4; ks++) {
        uint32_t a_hi[2][4], a_lo[2][4], b_hi[4][2], b_lo[4][2];
#pragma unroll
        for (int mf = 0; mf < 2; mf++) {
            ldsm4(sbase + 0     + laneA2 + (mwarp + mf*16)*144 + ks*32, a_hi[mf]);
            ldsm4(sbase + 18432 + laneA2 + (mwarp + mf*16)*144 + ks*32, a_lo[mf]);
        }
#pragma unroll
        for (int np = 0; np < 2; np++) {
            uint32_t r4[4];
            ldsm4(sbase + 36864 + laneB2 + (nwarp + np*16)*144 + ks*32, r4);
            b_hi[np*2][0] = r4[0]; b_hi[np*2][1] = r4[1]; b_hi[np*2+1][0] = r4[2]; b_hi[np*2+1][1] = r4[3];
            ldsm4(sbase + 46080 + laneB2 + (nwarp + np*16)*144 + ks*32, r4);
            b_lo[np*2][0] = r4[0]; b_lo[np*2][1] = r4[1]; b_lo[np*2+1][0] = r4[2]; b_lo[np*2+1][1] = r4[3];
        }
#pragma unroll
        for (int mf = 0; mf < 2; mf++)
#pragma unroll
            for (int nf = 0; nf < 4; nf++) {
                mma16816(acc2[mf][nf], a_hi[mf], b_hi[nf]);
                mma16816(acc2[mf][nf], a_lo[mf], b_hi[nf]);
                mma16816(acc2[mf][nf], a_hi[mf], b_lo[nf]);
            }
    }
    // z2 -> regs -> smem floats (stride 68) -> final dot
    float z2r[2][4][4];
    {
        int cb = nwarp + (lane & 3) * 2;
#pragma unroll
        for (int mf = 0; mf < 2; mf++)
#pragma unroll
            for (int nf = 0; nf < 4; nf++) {
                int col = cb + nf * 8;
                z2r[mf][nf][0] = lrelu(acc2[mf][nf][0] + cst[128+col]);
                z2r[mf][nf][1] = lrelu(acc2[mf][nf][1] + cst[128+col+1]);
                z2r[mf][nf][2] = lrelu(acc2[mf][nf][2] + cst[128+col]);
                z2r[mf][nf][3] = lrelu(acc2[mf][nf][3] + cst[128+col+1]);
            }
    }
    __syncthreads();
    float* z2f = (float*)sm;
    {
        int r0 = mwarp + (lane >> 2), cb = nwarp + (lane & 3) * 2;
#pragma unroll
        for (int mf = 0; mf < 2; mf++) {
            int r1 = r0 + mf*16, r2 = r1 + 8;
#pragma unroll
            for (int nf = 0; nf < 4; nf++) {
                int col = cb + nf * 8;
                *(float2*)&z2f[r1*68 + col] = make_float2(z2r[mf][nf][0], z2r[mf][nf][1]);
                *(float2*)&z2f[r2*68 + col] = make_float2(z2r[mf][nf][2], z2r[mf][nf][3]);
            }
        }
    }
    __syncthreads();
    {
        int cand = tid >> 1, half = tid & 1;
        float s = 0.f;
        const float* zr = &z2f[cand*68 + half*32];
        const float* wr = &cst[192 + half*32];
#pragma unroll
        for (int j = 0; j < 32; j++) s = fmaf(zr[j], wr[j], s);
        float other = __shfl_xor_sync(~0u, s, 1);
        if (half == 0) {
            int c = c0 + cand;
            if (c < CC) yout[c] = s + other + cst[384];
        }
    }
}

// ============ softmax ============
__global__ void k_max(const float* __restrict__ y) {
    float m = -3.402823466e38f;
    for (int i = blockIdx.x*blockDim.x+threadIdx.x; i < CC; i += gridDim.x*blockDim.x) m = fmaxf(m, y[i]);
#pragma unroll
    for (int o = 16; o > 0; o >>= 1) m = fmaxf(m, __shfl_xor_sync(~0u, m, o));
    __shared__ float sbuf[8];
    if ((threadIdx.x & 31) == 0) sbuf[threadIdx.x >> 5] = m;
    __syncthreads();
    if (threadIdx.x == 0) { float mm = sbuf[0]; for (int i = 1; i < 8; i++) mm = fmaxf(mm, sbuf[i]); atomicMax(&g_umax, fkey(mm)); }
}
__global__ void k_sum(const float* __restrict__ y) {
    float mx = fdec(g_umax), s = 0.f;
    for (int i = blockIdx.x*blockDim.x+threadIdx.x; i < CC; i += gridDim.x*blockDim.x) s += expf(y[i] - mx);
#pragma unroll
    for (int o = 16; o > 0; o >>= 1) s += __shfl_xor_sync(~0u, s, o);
    __shared__ float sbuf[8];
    if ((threadIdx.x & 31) == 0) sbuf[threadIdx.x >> 5] = s;
    __syncthreads();
    if (threadIdx.x == 0) { float t = 0.f; for (int i = 0; i < 8; i++) t += sbuf[i]; atomicAdd(&g_sum, t); }
}
__global__ void k_norm(const float* __restrict__ y, float* __restrict__ outp) {
    int i = blockIdx.x*blockDim.x+threadIdx.x;
    if (i < CC) outp[i] = expf(y[i] - fdec(g_umax)) * (1.f / g_sum);
}

// ============ launch ============
extern "C" void kernel_launch(void* const* d_in, const int* in_sizes, int n_in,
                              void* d_out, int out_size) {
    const float* x = (const float*)d_in[0];
    const int *src = (const int*)d_in[1], *dst = (const int*)d_in[2];
    const int *cu = (const int*)d_in[3], *cv = (const int*)d_in[4];
    const float* cf = (const float*)d_in[5];
    const float *ws0=(const float*)d_in[6], *wn0=(const float*)d_in[7], *b0=(const float*)d_in[8],
                *g0=(const float*)d_in[9], *be0=(const float*)d_in[10], *rm0=(const float*)d_in[11], *rv0=(const float*)d_in[12];
    const float *ws1=(const float*)d_in[13], *wn1=(const float*)d_in[14], *b1=(const float*)d_in[15],
                *g1=(const float*)d_in[16], *be1=(const float*)d_in[17], *rm1=(const float*)d_in[18], *rv1=(const float*)d_in[19];
    const float *mw0=(const float*)d_in[20], *mb0=(const float*)d_in[21], *mw1=(const float*)d_in[22],
                *mb1=(const float*)d_in[23], *mw2=(const float*)d_in[24], *mb2=(const float*)d_in[25];
    float* out = (float*)d_out;

    static bool attr_done = false;
    if (!attr_done) {
        cudaFuncSetAttribute(k_layer_mma, cudaFuncAttributeMaxDynamicSharedMemorySize, SM_LAYER_DB);
        cudaFuncSetAttribute(k_mlp_mma, cudaFuncAttributeMaxDynamicSharedMemorySize, SM_MLP);
        attr_done = true;
    }

    k_prep<<<(NN*DD+255)/256, 256>>>(x, ws0, wn0, ws1, wn1, mw0, mw1);
    k_count<<<(EE+255)/256, 256>>>(dst);
    k_scan<<<1, 1024>>>();
    k_fill<<<(EE+255)/256, 256>>>(src, dst);

    k_agg<<<(NN*32+255)/256, 256>>>(0, x);
    k_layer_mma<<<(NN+127)/128, 256, SM_LAYER_DB>>>(0, b0, g0, be0, rm0, rv0);
    k_agg<<<(NN*32+255)/256, 256>>>(1, x);
    k_layer_mma<<<(NN+127)/128, 256, SM_LAYER_DB>>>(1, b1, g1, be1, rm1, rv1);

    k_mlp_mma<<<(CC+127)/128, 256, SM_MLP>>>(cu, cv, cf, mw0, mb0, mb1, mw2, mb2, out);

    k_max<<<(CC+255)/256, 256>>>(out);
    k_sum<<<(CC+255)/256, 256>>>(out);
    if (out_size >= 2*CC) k_norm<<<(CC+255)/256, 256>>>(out, out + CC);
}

// round 10
// speedup vs baseline: 1.8595x; 1.0013x over previous
#include <cuda_runtime.h>
#include <cuda_bf16.h>
#include <cstdint>
#include <math.h>

#define NN 50000
#define EE 800000
#define CC 100000
#define DD 128

// ============ helpers ============
__device__ __forceinline__ uint32_t s2u(const void* p) {
    uint32_t a; asm("{ .reg .u64 t; cvta.to.shared.u64 t, %1; cvt.u32.u64 %0, t; }" : "=r"(a) : "l"(p)); return a;
}
__device__ __forceinline__ void ldsm4(uint32_t addr, uint32_t r[4]) {
    asm volatile("ldmatrix.sync.aligned.m8n8.x4.shared.b16 {%0,%1,%2,%3}, [%4];"
        : "=r"(r[0]), "=r"(r[1]), "=r"(r[2]), "=r"(r[3]) : "r"(addr));
}
__device__ __forceinline__ void mma16816(float c[4], const uint32_t a[4], const uint32_t b[2]) {
    asm volatile("mma.sync.aligned.m16n8k16.row.col.f32.bf16.bf16.f32 "
        "{%0,%1,%2,%3},{%4,%5,%6,%7},{%8,%9},{%0,%1,%2,%3};"
        : "+f"(c[0]), "+f"(c[1]), "+f"(c[2]), "+f"(c[3])
        : "r"(a[0]), "r"(a[1]), "r"(a[2]), "r"(a[3]), "r"(b[0]), "r"(b[1]));
}
__device__ __forceinline__ void cpa16(uint32_t dst, const void* src, int sz) {
    asm volatile("cp.async.cg.shared.global [%0], [%1], 16, %2;" :: "r"(dst), "l"(src), "r"(sz) : "memory");
}
#define CP_COMMIT() asm volatile("cp.async.commit_group;" ::: "memory")
#define CP_WAIT0()  asm volatile("cp.async.wait_group 0;" ::: "memory")
__device__ __forceinline__ uint32_t pack_hl(float a, float b, uint32_t& lo) {
    __nv_bfloat16 ha = __float2bfloat16(a), hb = __float2bfloat16(b);
    __nv_bfloat162 H; H.x = ha; H.y = hb;
    __nv_bfloat162 L; L.x = __float2bfloat16(a - __bfloat162float(ha));
    L.y = __float2bfloat16(b - __bfloat162float(hb));
    lo = reinterpret_cast<uint32_t&>(L);
    return reinterpret_cast<uint32_t&>(H);
}
__device__ __forceinline__ float lrelu(float v) { return v > 0.f ? v : 0.01f * v; }
__device__ __forceinline__ float postact(float v, int fix) {
    v = v > 0.f ? v : 0.01f * v;
    if (fix) { if (isnan(v)) v = 1e-14f; else if (isinf(v)) v = v > 0.f ? 3.402823466e38f : -3.402823466e38f; }
    return v;
}
__device__ __forceinline__ unsigned fkey(float f) { unsigned u = __float_as_uint(f); return (u & 0x80000000u) ? ~u : (u | 0x80000000u); }
__device__ __forceinline__ float fdec(unsigned u) { return (u & 0x80000000u) ? __uint_as_float(u & 0x7fffffffu) : __uint_as_float(~u); }

// ============ scratch ============
static __device__ float g_h0[NN * DD];
static __device__ float g_h1[NN * DD];
static __device__ __nv_bfloat16 g_xhi[NN*DD], g_xlo[NN*DD];
static __device__ __nv_bfloat16 g_h0hi[NN*DD], g_h0lo[NN*DD];
static __device__ __nv_bfloat16 g_aghi[NN*DD], g_aglo[NN*DD];
static __device__ __nv_bfloat16 g_W0hi[128*256], g_W0lo[128*256];
static __device__ __nv_bfloat16 g_W1hi[128*256], g_W1lo[128*256];
static __device__ __nv_bfloat16 g_M0hi[64*256], g_M0lo[64*256];
static __device__ __nv_bfloat16 g_M1hi[64*64], g_M1lo[64*64];
static __device__ int g_rowptr[NN+1], g_cursor[NN], g_cnt[NN], g_col[EE];
static __device__ float g_invdeg[NN];
static __device__ int g_pref[64];      // zero-init; self-resetting sentinel slots
static __device__ unsigned g_umax;
static __device__ float g_sum;

// ============ fused prep: conv_x + conv_w + edge count + softmax-state init ============
// NOTE: g_cnt is NOT zeroed here — it is zero from static init on run 1 and
// re-zeroed by k_scan at the end of every run (self-restoring invariant).
__global__ void k_prep(const float* __restrict__ x, const int* __restrict__ dst,
                       const float* __restrict__ ws0, const float* __restrict__ wn0,
                       const float* __restrict__ ws1, const float* __restrict__ wn1,
                       const float* __restrict__ mw0, const float* __restrict__ mw1) {
    int i = blockIdx.x*blockDim.x + threadIdx.x;
    if (i == 0) { g_umax = 0u; g_sum = 0.f; }
    if (i < EE) atomicAdd(&g_cnt[dst[i]], 1);
    if (i < NN*DD) {
        float v = x[i]; __nv_bfloat16 h = __float2bfloat16(v);
        g_xhi[i] = h; g_xlo[i] = __float2bfloat16(v - __bfloat162float(h));
    }
    if (i < 86016) {
        float v; __nv_bfloat16 *ph, *pl; int idx;
        if (i < 32768)      { int n = i>>8, k = i&255; v = (k<128) ? ws0[k*128+n] : wn0[(k-128)*128+n]; ph = g_W0hi; pl = g_W0lo; idx = i; }
        else if (i < 65536) { int j = i-32768, n = j>>8, k = j&255; v = (k<128) ? ws1[k*128+n] : wn1[(k-128)*128+n]; ph = g_W1hi; pl = g_W1lo; idx = j; }
        else if (i < 81920) { int j = i-65536, n = j>>8, k = j&255; v = mw0[k*64+n]; ph = g_M0hi; pl = g_M0lo; idx = j; }
        else                { int j = i-81920, n = j>>6, k = j&63;  v = mw1[k*64+n]; ph = g_M1hi; pl = g_M1lo; idx = j; }
        __nv_bfloat16 h = __float2bfloat16(v);
        ph[idx] = h; pl[idx] = __float2bfloat16(v - __bfloat162float(h));
    }
}

// ============ chained multi-block scan: 49 blocks x 1024 (all co-resident) ============
// Publishes prefix+1 into g_pref[b] (sentinel 0); consumer resets slot to 0,
// restoring the zero state for the next graph replay. Also zeroes g_cnt.
#define SCAN_BLOCKS 49
__global__ void k_scan() {
    __shared__ int wsum[32];
    __shared__ int sprefix;
    int b = blockIdx.x, t = threadIdx.x, lane = t & 31, w = t >> 5;
    int i = b * 1024 + t;
    int v = (i < NN) ? g_cnt[i] : 0;
    int x = v;
#pragma unroll
    for (int o = 1; o < 32; o <<= 1) { int y = __shfl_up_sync(~0u, x, o); if (lane >= o) x += y; }
    if (lane == 31) wsum[w] = x;
    __syncthreads();
    if (w == 0) {
        int s = wsum[lane];
#pragma unroll
        for (int o = 1; o < 32; o <<= 1) { int y = __shfl_up_sync(~0u, s, o); if (lane >= o) s += y; }
        wsum[lane] = s;
    }
    __syncthreads();
    int xin = x + (w ? wsum[w-1] : 0);      // inclusive within block
    int total = wsum[31];                    // block total
    if (t == 0) {
        int p = 0;
        if (b > 0) {
            int got;
            while ((got = atomicAdd(&g_pref[b-1], 0)) == 0) { }
            atomicExch(&g_pref[b-1], 0);     // reset slot for next replay
            p = got - 1;
        }
        sprefix = p;
        if (b < SCAN_BLOCKS - 1) { __threadfence(); atomicExch(&g_pref[b], p + total + 1); }
        else g_rowptr[NN] = p + total;
    }
    __syncthreads();
    int excl = sprefix + xin - v;
    if (i < NN) {
        g_rowptr[i] = excl; g_cursor[i] = excl;
        g_invdeg[i] = 1.0f / (float)(v > 1 ? v : 1);
        g_cnt[i] = 0;                        // restore for next replay
    }
}
__global__ void k_fill(const int* __restrict__ src, const int* __restrict__ dst) {
    int e = blockIdx.x*blockDim.x+threadIdx.x;
    if (e < EE) { int p = atomicAdd(&g_cursor[dst[e]], 1); g_col[p] = src[e]; }
}

// ============ aggregation -> bf16 hi/lo ============
__global__ void k_agg(int which, const float* __restrict__ x_ext) {
    int gw = (blockIdx.x*blockDim.x+threadIdx.x) >> 5, lane = threadIdx.x & 31;
    if (gw >= NN) return;
    const float* feat = which ? g_h0 : x_ext;
    int beg = g_rowptr[gw], end = g_rowptr[gw+1];
    float4 acc = make_float4(0.f, 0.f, 0.f, 0.f);
    for (int e = beg; e < end; ++e) {
        float4 v = *(const float4*)&feat[g_col[e]*DD + lane*4];
        acc.x += v.x; acc.y += v.y; acc.z += v.z; acc.w += v.w;
    }
    float id = g_invdeg[gw];
    acc.x *= id; acc.y *= id; acc.z *= id; acc.w *= id;
    uint32_t l01, l23, h01 = pack_hl(acc.x, acc.y, l01), h23 = pack_hl(acc.z, acc.w, l23);
    *(uint2*)&g_aghi[gw*DD + lane*4] = make_uint2(h01, h23);
    *(uint2*)&g_aglo[gw*DD + lane*4] = make_uint2(l01, l23);
}

// ============ SAGE layer: HMMA bf16x3, tile 128x128, K=256, cp.async double-buffer ============
#define SM_LAYER_DB 81920
__global__ __launch_bounds__(256) void k_layer_mma(int layer,
        const float* __restrict__ bb, const float* __restrict__ gm,
        const float* __restrict__ bt, const float* __restrict__ rm, const float* __restrict__ rv) {
    extern __shared__ __align__(16) uint8_t smdyn[];
    __shared__ float sS[128], sH[128];
    int tid = threadIdx.x, lane = tid & 31, wid = tid >> 5;
    const __nv_bfloat16 *Axh = layer ? g_h0hi : g_xhi, *Axl = layer ? g_h0lo : g_xlo;
    const __nv_bfloat16 *Wh = layer ? g_W1hi : g_W0hi, *Wl = layer ? g_W1lo : g_W0lo;
    float* hout = layer ? g_h1 : g_h0;
    if (tid < 128) {
        float s = gm[tid] * rsqrtf(rv[tid] + 1e-5f);
        sS[tid] = s; sH[tid] = (bb[tid] - rm[tid]) * s + bt[tid];
    }
    int m0 = blockIdx.x * 128;
    int mwarp = (wid & 3) * 32, nwarp = (wid >> 2) * 64;
    int g = lane >> 3, i = lane & 7;
    int laneA = (i + 8*(g & 1)) * 80 + (g >> 1) * 16;
    int laneB = (i + 8*(g >> 1)) * 80 + (g & 1) * 16;
    uint32_t sdyn = s2u(smdyn);
    float acc[2][8][4] = {};

    auto stage = [&](int c) {
        uint32_t buf = sdyn + (uint32_t)(c & 1) * 40960u;
        const __nv_bfloat16 *ah, *al; int kbA;
        if (c < 4) { ah = Axh; al = Axl; kbA = c * 32; } else { ah = g_aghi; al = g_aglo; kbA = (c - 4) * 32; }
        int kbB = c * 32;
        for (int it = tid; it < 512; it += 256) {
            int r = it >> 2, q = it & 3;
            int row = m0 + r;
            int rc = row < NN ? row : 0;
            int sz = row < NN ? 16 : 0;
            uint32_t so = (uint32_t)(r * 80 + q * 16);
            cpa16(buf + so,          &ah[rc*DD + kbA + q*8], sz);
            cpa16(buf + 10240 + so,  &al[rc*DD + kbA + q*8], sz);
            cpa16(buf + 20480 + so,  &Wh[r*256 + kbB + q*8], 16);
            cpa16(buf + 30720 + so,  &Wl[r*256 + kbB + q*8], 16);
        }
        CP_COMMIT();
    };

    stage(0);
    for (int c = 0; c < 8; c++) {
        CP_WAIT0();
        __syncthreads();
        if (c < 7) stage(c + 1);
        uint32_t buf = sdyn + (uint32_t)(c & 1) * 40960u;
        uint32_t aAh = buf, aAl = buf + 10240, aBh = buf + 20480, aBl = buf + 30720;
#pragma unroll
        for (int ks = 0; ks < 2; ks++) {
            uint32_t a_hi[2][4], a_lo[2][4], b_hi[8][2], b_lo[8][2];
#pragma unroll
            for (int mf = 0; mf < 2; mf++) {
                ldsm4(aAh + laneA + (mwarp + mf*16)*80 + ks*32, a_hi[mf]);
                ldsm4(aAl + laneA + (mwarp + mf*16)*80 + ks*32, a_lo[mf]);
            }
#pragma unroll
            for (int np = 0; np < 4; np++) {
                uint32_t r4[4];
                ldsm4(aBh + laneB + (nwarp + np*16)*80 + ks*32, r4);
                b_hi[np*2][0] = r4[0]; b_hi[np*2][1] = r4[1]; b_hi[np*2+1][0] = r4[2]; b_hi[np*2+1][1] = r4[3];
                ldsm4(aBl + laneB + (nwarp + np*16)*80 + ks*32, r4);
                b_lo[np*2][0] = r4[0]; b_lo[np*2][1] = r4[1]; b_lo[np*2+1][0] = r4[2]; b_lo[np*2+1][1] = r4[3];
            }
#pragma unroll
            for (int mf = 0; mf < 2; mf++)
#pragma unroll
                for (int nf = 0; nf < 8; nf++) {
                    mma16816(acc[mf][nf], a_hi[mf], b_hi[nf]);
                    mma16816(acc[mf][nf], a_lo[mf], b_hi[nf]);
                    mma16816(acc[mf][nf], a_hi[mf], b_lo[nf]);
                }
        }
        __syncthreads();
    }
    int r0 = mwarp + (lane >> 2), cb = nwarp + (lane & 3) * 2;
#pragma unroll
    for (int mf = 0; mf < 2; mf++) {
        int r1 = m0 + r0 + mf*16, r2 = r1 + 8;
#pragma unroll
        for (int nf = 0; nf < 8; nf++) {
            int col = cb + nf * 8;
            float s0 = sS[col], s1 = sS[col+1], h0 = sH[col], h1 = sH[col+1];
            if (r1 < NN) {
                float o0 = postact(acc[mf][nf][0]*s0 + h0, layer);
                float o1 = postact(acc[mf][nf][1]*s1 + h1, layer);
                *(float2*)&hout[r1*DD + col] = make_float2(o0, o1);
                if (!layer) { uint32_t l, h = pack_hl(o0, o1, l); *(uint32_t*)&g_h0hi[r1*DD + col] = h; *(uint32_t*)&g_h0lo[r1*DD + col] = l; }
            }
            if (r2 < NN) {
                float o0 = postact(acc[mf][nf][2]*s0 + h0, layer);
                float o1 = postact(acc[mf][nf][3]*s1 + h1, layer);
                *(float2*)&hout[r2*DD + col] = make_float2(o0, o1);
                if (!layer) { uint32_t l, h = pack_hl(o0, o1, l); *(uint32_t*)&g_h0hi[r2*DD + col] = h; *(uint32_t*)&g_h0lo[r2*DD + col] = l; }
            }
        }
    }
}

// ============ candidate MLP: HMMA bf16x3, 128 cands/block (+ fused softmax max) ============
#define SM_MLP 58368
__global__ __launch_bounds__(256) void k_mlp_mma(
        const int* __restrict__ cu, const int* __restrict__ cv, const float* __restrict__ cf,
        const float* __restrict__ mw0, const float* __restrict__ mb0,
        const float* __restrict__ mb1, const float* __restrict__ mw2,
        const float* __restrict__ mb2, float* __restrict__ yout) {
    extern __shared__ __align__(16) uint8_t sm[];
    float* cst = (float*)(sm + 55296);
    int* su = (int*)(sm + 56840);
    int* sv = (int*)(sm + 57352);
    int tid = threadIdx.x, lane = tid & 31, wid = tid >> 5;
    int c0 = blockIdx.x * 128;
    int mwarp = (wid & 3) * 32, nwarp = (wid >> 2) * 32;
    int g = lane >> 3, i = lane & 7;
    int laneA  = (i + 8*(g & 1)) * 80 + (g >> 1) * 16;
    int laneB  = (i + 8*(g >> 1)) * 80 + (g & 1) * 16;
    int laneA2 = (i + 8*(g & 1)) * 144 + (g >> 1) * 16;
    int laneB2 = (i + 8*(g >> 1)) * 144 + (g & 1) * 16;
    uint32_t sbase = s2u(sm);

    if (tid < 64) {
        cst[tid]       = mb0[tid];
        cst[64 + tid]  = mw0[256*64 + tid];
        cst[128 + tid] = mb1[tid];
        cst[192 + tid] = mw2[tid];
    }
    if (tid == 0) cst[384] = mb2[0];
    if (tid < 128) {
        int c = c0 + tid;
        su[tid] = (c < CC) ? cu[c] : 0;
        sv[tid] = (c < CC) ? cv[c] : 0;
        cst[256 + tid] = (c < CC) ? cf[c] : 0.f;
    }
    for (int it = tid; it < 512; it += 256) {
        int r = it >> 3, q = it & 7;
        *(uint4*)(sm + 36864 + r*144 + q*16) = *(const uint4*)&g_M1hi[r*64 + q*8];
        *(uint4*)(sm + 46080 + r*144 + q*16) = *(const uint4*)&g_M1lo[r*64 + q*8];
    }

    float acc[2][4][4] = {};
    for (int c = 0; c < 8; c++) {
        int kbA = (c < 4) ? c * 32 : (c - 4) * 32;
        int kbB = c * 32;
        const int* sel = (c < 4) ? su : sv;
        __syncthreads();
        for (int it = tid; it < 1024; it += 256) {
            int r = it >> 3, q = it & 7;
            int node = sel[r];
            float4 v = *(const float4*)&g_h1[node*DD + kbA + q*4];
            uint32_t l01, l23, h01 = pack_hl(v.x, v.y, l01), h23 = pack_hl(v.z, v.w, l23);
            *(uint2*)(sm + 0     + r*80 + q*8) = make_uint2(h01, h23);
            *(uint2*)(sm + 10240 + r*80 + q*8) = make_uint2(l01, l23);
            if (it < 256) {
                int rr = it >> 2, qq = it & 3;
                *(uint4*)(sm + 20480 + rr*80 + qq*16) = *(const uint4*)&g_M0hi[rr*256 + kbB + qq*8];
                *(uint4*)(sm + 25600 + rr*80 + qq*16) = *(const uint4*)&g_M0lo[rr*256 + kbB + qq*8];
            }
        }
        __syncthreads();
#pragma unroll
        for (int ks = 0; ks < 2; ks++) {
            uint32_t a_hi[2][4], a_lo[2][4], b_hi[4][2], b_lo[4][2];
#pragma unroll
            for (int mf = 0; mf < 2; mf++) {
                ldsm4(sbase + 0     + laneA + (mwarp + mf*16)*80 + ks*32, a_hi[mf]);
                ldsm4(sbase + 10240 + laneA + (mwarp + mf*16)*80 + ks*32, a_lo[mf]);
            }
#pragma unroll
            for (int np = 0; np < 2; np++) {
                uint32_t r4[4];
                ldsm4(sbase + 20480 + laneB + (nwarp + np*16)*80 + ks*32, r4);
                b_hi[np*2][0] = r4[0]; b_hi[np*2][1] = r4[1]; b_hi[np*2+1][0] = r4[2]; b_hi[np*2+1][1] = r4[3];
                ldsm4(sbase + 25600 + laneB + (nwarp + np*16)*80 + ks*32, r4);
                b_lo[np*2][0] = r4[0]; b_lo[np*2][1] = r4[1]; b_lo[np*2+1][0] = r4[2]; b_lo[np*2+1][1] = r4[3];
            }
#pragma unroll
            for (int mf = 0; mf < 2; mf++)
#pragma unroll
                for (int nf = 0; nf < 4; nf++) {
                    mma16816(acc[mf][nf], a_hi[mf], b_hi[nf]);
                    mma16816(acc[mf][nf], a_lo[mf], b_hi[nf]);
                    mma16816(acc[mf][nf], a_hi[mf], b_lo[nf]);
                }
        }
    }
    __syncthreads();
    {
        int r0 = mwarp + (lane >> 2), cb = nwarp + (lane & 3) * 2;
#pragma unroll
        for (int mf = 0; mf < 2; mf++) {
            int r1 = r0 + mf*16, r2 = r1 + 8;
            float fz1 = cst[256 + r1], fz2 = cst[256 + r2];
#pragma unroll
            for (int nf = 0; nf < 4; nf++) {
                int col = cb + nf * 8;
                float b0v = cst[col], b1v = cst[col+1], w0 = cst[64+col], w1 = cst[64+col+1];
                float z0 = lrelu(acc[mf][nf][0] + b0v + fz1 * w0);
                float z1 = lrelu(acc[mf][nf][1] + b1v + fz1 * w1);
                uint32_t l, h = pack_hl(z0, z1, l);
                *(uint32_t*)(sm + 0     + r1*144 + col*2) = h;
                *(uint32_t*)(sm + 18432 + r1*144 + col*2) = l;
                z0 = lrelu(acc[mf][nf][2] + b0v + fz2 * w0);
                z1 = lrelu(acc[mf][nf][3] + b1v + fz2 * w1);
                h = pack_hl(z0, z1, l);
                *(uint32_t*)(sm + 0     + r2*144 + col*2) = h;
                *(uint32_t*)(sm + 18432 + r2*144 + col*2) = l;
            }
        }
    }
    __syncthreads();

    float acc2[2][4][4] = {};
#pragma unroll
    for (int ks = 0; ks < 4; ks++) {
        uint32_t a_hi[2][4], a_lo[2][4], b_hi[4][2], b_lo[4][2];
#pragma unroll
        for (int mf = 0; mf < 2; mf++) {
            ldsm4(sbase + 0     + laneA2 + (mwarp + mf*16)*144 + ks*32, a_hi[mf]);
            ldsm4(sbase + 18432 + laneA2 + (mwarp + mf*16)*144 + ks*32, a_lo[mf]);
        }
#pragma unroll
        for (int np = 0; np < 2; np++) {
            uint32_t r4[4];
            ldsm4(sbase + 36864 + laneB2 + (nwarp + np*16)*144 + ks*32, r4);
            b_hi[np*2][0] = r4[0]; b_hi[np*2][1] = r4[1]; b_hi[np*2+1][0] = r4[2]; b_hi[np*2+1][1] = r4[3];
            ldsm4(sbase + 46080 + laneB2 + (nwarp + np*16)*144 + ks*32, r4);
            b_lo[np*2][0] = r4[0]; b_lo[np*2][1] = r4[1]; b_lo[np*2+1][0] = r4[2]; b_lo[np*2+1][1] = r4[3];
        }
#pragma unroll
        for (int mf = 0; mf < 2; mf++)
#pragma unroll
            for (int nf = 0; nf < 4; nf++) {
                mma16816(acc2[mf][nf], a_hi[mf], b_hi[nf]);
                mma16816(acc2[mf][nf], a_lo[mf], b_hi[nf]);
                mma16816(acc2[mf][nf], a_hi[mf], b_lo[nf]);
            }
    }
    float z2r[2][4][4];
    {
        int cb = nwarp + (lane & 3) * 2;
#pragma unroll
        for (int mf = 0; mf < 2; mf++)
#pragma unroll
            for (int nf = 0; nf < 4; nf++) {
                int col = cb + nf * 8;
                z2r[mf][nf][0] = lrelu(acc2[mf][nf][0] + cst[128+col]);
                z2r[mf][nf][1] = lrelu(acc2[mf][nf][1] + cst[128+col+1]);
                z2r[mf][nf][2] = lrelu(acc2[mf][nf][2] + cst[128+col]);
                z2r[mf][nf][3] = lrelu(acc2[mf][nf][3] + cst[128+col+1]);
            }
    }
    __syncthreads();
    float* z2f = (float*)sm;
    {
        int r0 = mwarp + (lane >> 2), cb = nwarp + (lane & 3) * 2;
#pragma unroll
        for (int mf = 0; mf < 2; mf++) {
            int r1 = r0 + mf*16, r2 = r1 + 8;
#pragma unroll
            for (int nf = 0; nf < 4; nf++) {
                int col = cb + nf * 8;
                *(float2*)&z2f[r1*68 + col] = make_float2(z2r[mf][nf][0], z2r[mf][nf][1]);
                *(float2*)&z2f[r2*68 + col] = make_float2(z2r[mf][nf][2], z2r[mf][nf][3]);
            }
        }
    }
    __syncthreads();
    {
        int cand = tid >> 1, half = tid & 1;
        float s = 0.f;
        const float* zr = &z2f[cand*68 + half*32];
        const float* wr = &cst[192 + half*32];
#pragma unroll
        for (int j = 0; j < 32; j++) s = fmaf(zr[j], wr[j], s);
        float other = __shfl_xor_sync(~0u, s, 1);
        float m = -3.402823466e38f;
        if (half == 0) {
            int c = c0 + cand;
            if (c < CC) { float y = s + other + cst[384]; yout[c] = y; m = y; }
        }
        // fused softmax max: block-reduce m, one atomicMax per block
#pragma unroll
        for (int o = 16; o > 0; o >>= 1) m = fmaxf(m, __shfl_xor_sync(~0u, m, o));
        __shared__ float smax[8];
        if (lane == 0) smax[wid] = m;
        __syncthreads();
        if (tid == 0) {
            float mm = smax[0];
#pragma unroll
            for (int j = 1; j < 8; j++) mm = fmaxf(mm, smax[j]);
            atomicMax(&g_umax, fkey(mm));
        }
    }
}

// ============ softmax tail ============
__global__ void k_sum(const float* __restrict__ y) {
    float mx = fdec(g_umax), s = 0.f;
    for (int i = blockIdx.x*blockDim.x+threadIdx.x; i < CC; i += gridDim.x*blockDim.x) s += expf(y[i] - mx);
#pragma unroll
    for (int o = 16; o > 0; o >>= 1) s += __shfl_xor_sync(~0u, s, o);
    __shared__ float sbuf[8];
    if ((threadIdx.x & 31) == 0) sbuf[threadIdx.x >> 5] = s;
    __syncthreads();
    if (threadIdx.x == 0) { float t = 0.f; for (int i = 0; i < 8; i++) t += sbuf[i]; atomicAdd(&g_sum, t); }
}
__global__ void k_norm(const float* __restrict__ y, float* __restrict__ outp) {
    int i = blockIdx.x*blockDim.x+threadIdx.x;
    if (i < CC) outp[i] = expf(y[i] - fdec(g_umax)) * (1.f / g_sum);
}

// ============ launch ============
extern "C" void kernel_launch(void* const* d_in, const int* in_sizes, int n_in,
                              void* d_out, int out_size) {
    const float* x = (const float*)d_in[0];
    const int *src = (const int*)d_in[1], *dst = (const int*)d_in[2];
    const int *cu = (const int*)d_in[3], *cv = (const int*)d_in[4];
    const float* cf = (const float*)d_in[5];
    const float *ws0=(const float*)d_in[6], *wn0=(const float*)d_in[7], *b0=(const float*)d_in[8],
                *g0=(const float*)d_in[9], *be0=(const float*)d_in[10], *rm0=(const float*)d_in[11], *rv0=(const float*)d_in[12];
    const float *ws1=(const float*)d_in[13], *wn1=(const float*)d_in[14], *b1=(const float*)d_in[15],
                *g1=(const float*)d_in[16], *be1=(const float*)d_in[17], *rm1=(const float*)d_in[18], *rv1=(const float*)d_in[19];
    const float *mw0=(const float*)d_in[20], *mb0=(const float*)d_in[21], *mw1=(const float*)d_in[22],
                *mb1=(const float*)d_in[23], *mw2=(const float*)d_in[24], *mb2=(const float*)d_in[25];
    float* out = (float*)d_out;

    static bool attr_done = false;
    if (!attr_done) {
        cudaFuncSetAttribute(k_layer_mma, cudaFuncAttributeMaxDynamicSharedMemorySize, SM_LAYER_DB);
        cudaFuncSetAttribute(k_mlp_mma, cudaFuncAttributeMaxDynamicSharedMemorySize, SM_MLP);
        attr_done = true;
    }

    k_prep<<<(NN*DD+255)/256, 256>>>(x, dst, ws0, wn0, ws1, wn1, mw0, mw1);
    k_scan<<<SCAN_BLOCKS, 1024>>>();
    k_fill<<<(EE+255)/256, 256>>>(src, dst);

    k_agg<<<(NN*32+255)/256, 256>>>(0, x);
    k_layer_mma<<<(NN+127)/128, 256, SM_LAYER_DB>>>(0, b0, g0, be0, rm0, rv0);
    k_agg<<<(NN*32+255)/256, 256>>>(1, x);
    k_layer_mma<<<(NN+127)/128, 256, SM_LAYER_DB>>>(1, b1, g1, be1, rm1, rv1);

    k_mlp_mma<<<(CC+127)/128, 256, SM_MLP>>>(cu, cv, cf, mw0, mb0, mb1, mw2, mb2, out);

    k_sum<<<(CC+255)/256, 256>>>(out);
    if (out_size >= 2*CC) k_norm<<<(CC+255)/256, 256>>>(out, out + CC);
}